// round 1
// baseline (speedup 1.0000x reference)
#include <cuda_runtime.h>
#include <cstdint>

// Problem constants
#define BB 4
#define TT 2048
#define CC 1024
#define NH 16
#define HD 64
#define MROWS (BB * TT)   // 8192

// Scratch (device globals — no cudaMalloc allowed)
__device__ float g_qkv[(size_t)MROWS * 3 * CC];   // [B*T, 3072]
__device__ float g_att[(size_t)MROWS * CC];       // [B*T, 1024] attention output (pre-proj)

// ---------------------------------------------------------------------------
// GEMM: C[m,n] = sum_k A[m,k] * W[n,k] + bias[n]
// A: [M,K] row-major, W: [N,K] row-major (torch Linear weight), both K-contiguous.
// 128x128 tile, BK=8, 8x8 per thread, 256 threads.
// ---------------------------------------------------------------------------
__global__ __launch_bounds__(256) void sgemm_nt_bias(
    const float* __restrict__ A, const float* __restrict__ W,
    const float* __restrict__ bias, float* __restrict__ C,
    int M, int N, int K)
{
    constexpr int BM = 128, BN = 128, BK = 8, TM = 8, TN = 8;
    __shared__ float As[BK][BM];
    __shared__ float Ws[BK][BN];

    const int tid  = threadIdx.x;
    const int tx   = tid & 15;        // 0..15 → n sub-tile
    const int ty   = tid >> 4;        // 0..15 → m sub-tile
    const int mblk = blockIdx.y * BM;
    const int nblk = blockIdx.x * BN;

    // Loader mapping: 256 threads cover 128 rows x 2 float4 (8 floats) each
    const int lrow = tid >> 1;        // 0..127
    const int lcol = (tid & 1) * 4;   // 0 or 4
    const float* Ap = A + (size_t)(mblk + lrow) * K + lcol;
    const float* Wp = W + (size_t)(nblk + lrow) * K + lcol;

    float acc[TM][TN];
    #pragma unroll
    for (int i = 0; i < TM; i++)
        #pragma unroll
        for (int j = 0; j < TN; j++)
            acc[i][j] = 0.0f;

    for (int k0 = 0; k0 < K; k0 += BK) {
        float4 a4 = *(const float4*)(Ap + k0);
        float4 w4 = *(const float4*)(Wp + k0);
        As[lcol + 0][lrow] = a4.x;
        As[lcol + 1][lrow] = a4.y;
        As[lcol + 2][lrow] = a4.z;
        As[lcol + 3][lrow] = a4.w;
        Ws[lcol + 0][lrow] = w4.x;
        Ws[lcol + 1][lrow] = w4.y;
        Ws[lcol + 2][lrow] = w4.z;
        Ws[lcol + 3][lrow] = w4.w;
        __syncthreads();

        #pragma unroll
        for (int kk = 0; kk < BK; kk++) {
            float ra[TM], rb[TN];
            #pragma unroll
            for (int i = 0; i < TM; i += 4)
                *(float4*)&ra[i] = *(const float4*)&As[kk][ty * TM + i];
            #pragma unroll
            for (int j = 0; j < TN; j += 4)
                *(float4*)&rb[j] = *(const float4*)&Ws[kk][tx * TN + j];
            #pragma unroll
            for (int i = 0; i < TM; i++)
                #pragma unroll
                for (int j = 0; j < TN; j++)
                    acc[i][j] += ra[i] * rb[j];
        }
        __syncthreads();
    }

    // Epilogue: add bias, vectorized store
    #pragma unroll
    for (int i = 0; i < TM; i++) {
        const int m = mblk + ty * TM + i;
        #pragma unroll
        for (int j = 0; j < TN; j += 4) {
            const int n = nblk + tx * TN + j;
            float4 o;
            o.x = acc[i][j + 0] + bias[n + 0];
            o.y = acc[i][j + 1] + bias[n + 1];
            o.z = acc[i][j + 2] + bias[n + 2];
            o.w = acc[i][j + 3] + bias[n + 3];
            *(float4*)&C[(size_t)m * N + n] = o;
        }
    }
}

// ---------------------------------------------------------------------------
// Flash attention (causal, fp32). One block = 64 q-rows of one (b,h).
// Thread i owns q-row q0+i fully in registers. KV staged in smem tiles of 32.
// qkv layout: [B*T, 3072]; q at col h*64, k at 1024+h*64, v at 2048+h*64.
// Output written to g_att in [B*T, 1024] layout (head-interleaved) so the
// projection GEMM reads it directly.
// ---------------------------------------------------------------------------
__global__ __launch_bounds__(64) void flash_attn_fp32(
    const float* __restrict__ qkv, float* __restrict__ out)
{
    __shared__ float Ks[32][64];
    __shared__ float Vs[32][64];

    const int tid = threadIdx.x;
    const int bh  = blockIdx.y;
    const int b   = bh >> 4;
    const int h   = bh & 15;
    // Reverse q-tile order: heaviest (longest causal span) blocks first.
    const int qblk = (int)gridDim.x - 1 - (int)blockIdx.x;
    const int q0   = qblk * 64;
    const int row  = q0 + tid;

    const float SCALE = 0.125f;  // 1/sqrt(64)

    // Load q row into registers, pre-scaled
    const float* qrow = qkv + (size_t)(b * TT + row) * (3 * CC) + h * HD;
    float q[HD];
    #pragma unroll
    for (int k = 0; k < HD; k += 4) {
        float4 v = *(const float4*)(qrow + k);
        q[k + 0] = v.x * SCALE;
        q[k + 1] = v.y * SCALE;
        q[k + 2] = v.z * SCALE;
        q[k + 3] = v.w * SCALE;
    }

    float o[HD];
    #pragma unroll
    for (int k = 0; k < HD; k++) o[k] = 0.0f;
    float mi = -__int_as_float(0x7f800000);  // -inf
    float li = 0.0f;

    const int ntiles = (q0 + 64) / 32;  // causal: kv rows [0, q0+64)

    for (int t = 0; t < ntiles; t++) {
        const int s0 = t * 32;
        // Cooperative load of K,V tile: 32 rows x 64 cols each
        const float* kbase = qkv + (size_t)(b * TT + s0) * (3 * CC) + CC + h * HD;
        const float* vbase = kbase + CC;
        #pragma unroll
        for (int j = 0; j < 8; j++) {
            const int idx4 = tid + j * 64;       // 0..511
            const int r = idx4 >> 4;             // 0..31
            const int c = (idx4 & 15) * 4;       // 0..60
            *(float4*)&Ks[r][c] = *(const float4*)(kbase + (size_t)r * (3 * CC) + c);
            *(float4*)&Vs[r][c] = *(const float4*)(vbase + (size_t)r * (3 * CC) + c);
        }
        __syncthreads();

        // s[j] = q . K[j]  (uniform smem addresses across warp → broadcast)
        float s[32];
        #pragma unroll
        for (int j = 0; j < 32; j++) {
            float a = 0.0f;
            #pragma unroll
            for (int k = 0; k < HD; k += 4) {
                float4 kv = *(const float4*)&Ks[j][k];
                a += q[k]     * kv.x;
                a += q[k + 1] * kv.y;
                a += q[k + 2] * kv.z;
                a += q[k + 3] * kv.w;
            }
            s[j] = (s0 + j <= row) ? a : -__int_as_float(0x7f800000);
        }

        // Online softmax update
        float mt = mi;
        #pragma unroll
        for (int j = 0; j < 32; j++) mt = fmaxf(mt, s[j]);
        const float rescale = __expf(mi - mt);
        li *= rescale;
        #pragma unroll
        for (int k = 0; k < HD; k++) o[k] *= rescale;

        float psum = 0.0f;
        #pragma unroll
        for (int j = 0; j < 32; j++) {
            const float p = __expf(s[j] - mt);
            s[j] = p;
            psum += p;
        }
        li += psum;
        mi = mt;

        // o += P @ V
        #pragma unroll
        for (int j = 0; j < 32; j++) {
            const float p = s[j];
            #pragma unroll
            for (int k = 0; k < HD; k += 4) {
                float4 vv = *(const float4*)&Vs[j][k];
                o[k + 0] += p * vv.x;
                o[k + 1] += p * vv.y;
                o[k + 2] += p * vv.z;
                o[k + 3] += p * vv.w;
            }
        }
        __syncthreads();
    }

    const float inv = 1.0f / li;
    float* orow = out + (size_t)(b * TT + row) * CC + h * HD;
    #pragma unroll
    for (int k = 0; k < HD; k += 4) {
        float4 v;
        v.x = o[k + 0] * inv;
        v.y = o[k + 1] * inv;
        v.z = o[k + 2] * inv;
        v.w = o[k + 3] * inv;
        *(float4*)(orow + k) = v;
    }
}

// ---------------------------------------------------------------------------
extern "C" void kernel_launch(void* const* d_in, const int* in_sizes, int n_in,
                              void* d_out, int out_size)
{
    const float* x      = (const float*)d_in[0];  // [4,2048,1024]
    const float* W_qkv  = (const float*)d_in[1];  // [3072,1024]
    const float* b_qkv  = (const float*)d_in[2];  // [3072]
    const float* W_proj = (const float*)d_in[3];  // [1024,1024]
    const float* b_proj = (const float*)d_in[4];  // [1024]
    float* out = (float*)d_out;                   // [4,2048,1024]

    float *qkv_ptr = nullptr, *att_ptr = nullptr;
    cudaGetSymbolAddress((void**)&qkv_ptr, g_qkv);
    cudaGetSymbolAddress((void**)&att_ptr, g_att);

    // 1) QKV projection: [8192,1024] @ [3072,1024]^T + b → [8192,3072]
    {
        dim3 grid((3 * CC) / 128, MROWS / 128);  // (24, 64)
        sgemm_nt_bias<<<grid, 256>>>(x, W_qkv, b_qkv, qkv_ptr, MROWS, 3 * CC, CC);
    }
    // 2) Causal flash attention → g_att [8192,1024]
    {
        dim3 grid(TT / 64, BB * NH);             // (32, 64)
        flash_attn_fp32<<<grid, 64>>>(qkv_ptr, att_ptr);
    }
    // 3) Output projection: [8192,1024] @ [1024,1024]^T + b → d_out
    {
        dim3 grid(CC / 128, MROWS / 128);        // (8, 64)
        sgemm_nt_bias<<<grid, 256>>>(att_ptr, W_proj, b_proj, out, MROWS, CC, CC);
    }
}

// round 3
// speedup vs baseline: 1.3824x; 1.3824x over previous
#include <cuda_runtime.h>
#include <cuda_bf16.h>
#include <cstdint>

// Problem constants
#define BB 4
#define TT 2048
#define CC 1024
#define NH 16
#define HD 64
#define MROWS (BB * TT)   // 8192

// ---------------------------------------------------------------------------
// Scratch (device globals — no cudaMalloc allowed)
// ---------------------------------------------------------------------------
__device__ float g_qkv[(size_t)MROWS * 3 * CC];            // [8192, 3072] fp32
__device__ float g_att[(size_t)MROWS * CC];                // [8192, 1024] fp32
__device__ __nv_bfloat16 g_x_hi[(size_t)MROWS * CC];
__device__ __nv_bfloat16 g_x_lo[(size_t)MROWS * CC];
__device__ __nv_bfloat16 g_wqkv_hi[(size_t)3 * CC * CC];
__device__ __nv_bfloat16 g_wqkv_lo[(size_t)3 * CC * CC];
__device__ __nv_bfloat16 g_wproj_hi[(size_t)CC * CC];
__device__ __nv_bfloat16 g_wproj_lo[(size_t)CC * CC];
__device__ __nv_bfloat16 g_att_hi[(size_t)MROWS * CC];
__device__ __nv_bfloat16 g_att_lo[(size_t)MROWS * CC];

// ---------------------------------------------------------------------------
// Helpers
// ---------------------------------------------------------------------------
__device__ __forceinline__ uint32_t smem_to_u32(const void* p) {
    uint32_t a;
    asm("{ .reg .u64 t; cvta.to.shared.u64 t, %1; cvt.u32.u64 %0, t; }" : "=r"(a) : "l"(p));
    return a;
}

#define CP_ASYNC_16(dst_u32, src_ptr) \
    asm volatile("cp.async.cg.shared.global [%0], [%1], 16;" \
        :: "r"(dst_u32), "l"(src_ptr) : "memory")
#define CP_ASYNC_COMMIT() asm volatile("cp.async.commit_group;" ::: "memory")
#define CP_ASYNC_WAIT(n)  asm volatile("cp.async.wait_group %0;" :: "n"(n) : "memory")

__device__ __forceinline__ void ldsm4(uint32_t* r, uint32_t addr) {
    asm volatile("ldmatrix.sync.aligned.m8n8.x4.shared.b16 {%0,%1,%2,%3}, [%4];"
        : "=r"(r[0]), "=r"(r[1]), "=r"(r[2]), "=r"(r[3]) : "r"(addr));
}

__device__ __forceinline__ void mma_bf16(float* c, const uint32_t* a, const uint32_t* b) {
    asm volatile(
        "mma.sync.aligned.m16n8k16.row.col.f32.bf16.bf16.f32 "
        "{%0,%1,%2,%3}, {%4,%5,%6,%7}, {%8,%9}, {%0,%1,%2,%3};"
        : "+f"(c[0]), "+f"(c[1]), "+f"(c[2]), "+f"(c[3])
        : "r"(a[0]), "r"(a[1]), "r"(a[2]), "r"(a[3]), "r"(b[0]), "r"(b[1]));
}

// ---------------------------------------------------------------------------
// fp32 -> (bf16 hi, bf16 lo) split.
// ---------------------------------------------------------------------------
__global__ __launch_bounds__(256) void split_bf16_kernel(
    const float* __restrict__ in,
    __nv_bfloat16* __restrict__ hi, __nv_bfloat16* __restrict__ lo, int n4)
{
    int i = blockIdx.x * blockDim.x + threadIdx.x;
    if (i >= n4) return;
    float4 v = ((const float4*)in)[i];
    __nv_bfloat16 h0 = __float2bfloat16(v.x);
    __nv_bfloat16 h1 = __float2bfloat16(v.y);
    __nv_bfloat16 h2 = __float2bfloat16(v.z);
    __nv_bfloat16 h3 = __float2bfloat16(v.w);
    __nv_bfloat16 l0 = __float2bfloat16(v.x - __bfloat162float(h0));
    __nv_bfloat16 l1 = __float2bfloat16(v.y - __bfloat162float(h1));
    __nv_bfloat16 l2 = __float2bfloat16(v.z - __bfloat162float(h2));
    __nv_bfloat16 l3 = __float2bfloat16(v.w - __bfloat162float(h3));
    __nv_bfloat162 hA; hA.x = h0; hA.y = h1;
    __nv_bfloat162 hB; hB.x = h2; hB.y = h3;
    __nv_bfloat162 lA; lA.x = l0; lA.y = l1;
    __nv_bfloat162 lB; lB.x = l2; lB.y = l3;
    ((__nv_bfloat162*)hi)[2 * i]     = hA;
    ((__nv_bfloat162*)hi)[2 * i + 1] = hB;
    ((__nv_bfloat162*)lo)[2 * i]     = lA;
    ((__nv_bfloat162*)lo)[2 * i + 1] = lB;
}

// ---------------------------------------------------------------------------
// bf16x3 GEMM via mma.sync:  C[m,n] = sum_k A[m,k]*W[n,k] + bias[n]
// A = Ahi+Alo, W = Bhi+Blo.  CTA 128x128, BK=32, 8 warps (2m x 4n),
// warp tile 64x32 (m16n8k16), cp.async 2-stage double buffer.
// SMEM rows padded to 80B -> conflict-free ldmatrix.
// ---------------------------------------------------------------------------
#define ROW_B   80                 // bytes per smem row (32 bf16 + 8 pad)
#define TILE_B  (128 * ROW_B)      // 10240 bytes per tile
#define STAGE_B (4 * TILE_B)       // Ahi, Alo, Bhi, Blo
#define GEMM_SMEM (2 * STAGE_B)    // 81920

__global__ __launch_bounds__(256) void gemm_bf16x3_mma(
    const __nv_bfloat16* __restrict__ Ahi, const __nv_bfloat16* __restrict__ Alo,
    const __nv_bfloat16* __restrict__ Bhi, const __nv_bfloat16* __restrict__ Blo,
    const float* __restrict__ bias, float* __restrict__ C,
    int K, int N)
{
    extern __shared__ __align__(16) char smem[];
    const uint32_t sbase = smem_to_u32(smem);
    const int tid = threadIdx.x;
    const int wid = tid >> 5;
    const int lid = tid & 31;
    const int wm  = wid & 1;          // 0..1  (m)
    const int wn  = wid >> 1;         // 0..3  (n)
    const int m0  = blockIdx.y * 128;
    const int n0  = blockIdx.x * 128;

    // Loader mapping: thread covers rows r0 and r0+64 at 16B-chunk column cc.
    const int lr = tid >> 2;          // 0..63
    const int cc = tid & 3;           // 0..3
    const uint32_t sm_off = (uint32_t)lr * ROW_B + (uint32_t)cc * 16;
    const int gcol = cc * 8;          // element offset within the 32-wide K chunk

    // ldmatrix per-lane offsets
    const uint32_t a_off = (uint32_t)(wm * 64 + (lid & 15)) * ROW_B + (uint32_t)(lid >> 4) * 16;
    const uint32_t b_off = (uint32_t)(wn * 32 + ((lid >> 4) << 3) + (lid & 7)) * ROW_B
                         + (uint32_t)((lid >> 3) & 1) * 16;

    float acc[4][4][4];
    #pragma unroll
    for (int i = 0; i < 4; i++)
        #pragma unroll
        for (int n = 0; n < 4; n++)
            #pragma unroll
            for (int v = 0; v < 4; v++)
                acc[i][n][v] = 0.0f;

    const int NCHUNK = K >> 5;  // K/32

    // ---- stage loader ----
    auto load_stage = [&](int s, int k0) {
        const uint32_t st = sbase + (uint32_t)s * STAGE_B;
        const size_t ga = (size_t)(m0 + lr) * K + k0 + gcol;
        const size_t gb = (size_t)(n0 + lr) * K + k0 + gcol;
        CP_ASYNC_16(st + sm_off,                          Ahi + ga);
        CP_ASYNC_16(st + sm_off + 64u * ROW_B,            Ahi + ga + (size_t)64 * K);
        CP_ASYNC_16(st + TILE_B + sm_off,                 Alo + ga);
        CP_ASYNC_16(st + TILE_B + sm_off + 64u * ROW_B,   Alo + ga + (size_t)64 * K);
        CP_ASYNC_16(st + 2u * TILE_B + sm_off,                        Bhi + gb);
        CP_ASYNC_16(st + 2u * TILE_B + sm_off + 64u * ROW_B,          Bhi + gb + (size_t)64 * K);
        CP_ASYNC_16(st + 3u * TILE_B + sm_off,                        Blo + gb);
        CP_ASYNC_16(st + 3u * TILE_B + sm_off + 64u * ROW_B,          Blo + gb + (size_t)64 * K);
    };

    load_stage(0, 0);
    CP_ASYNC_COMMIT();

    for (int c = 0; c < NCHUNK; c++) {
        if (c + 1 < NCHUNK) {
            load_stage((c + 1) & 1, (c + 1) << 5);
            CP_ASYNC_COMMIT();
            CP_ASYNC_WAIT(1);
        } else {
            CP_ASYNC_WAIT(0);
        }
        __syncthreads();

        const uint32_t st  = sbase + (uint32_t)(c & 1) * STAGE_B;
        const uint32_t aHi = st + a_off;
        const uint32_t aLo = st + TILE_B + a_off;
        const uint32_t bHi = st + 2u * TILE_B + b_off;
        const uint32_t bLo = st + 3u * TILE_B + b_off;

        #pragma unroll
        for (int kk = 0; kk < 2; kk++) {
            const uint32_t kb = (uint32_t)kk * 32;  // 16 bf16 = 32 bytes
            uint32_t ahi[4][4], alo[4][4];
            #pragma unroll
            for (int i = 0; i < 4; i++) {
                ldsm4(ahi[i], aHi + (uint32_t)i * 16 * ROW_B + kb);
                ldsm4(alo[i], aLo + (uint32_t)i * 16 * ROW_B + kb);
            }
            uint32_t bhi[2][4], blo[2][4];
            #pragma unroll
            for (int j = 0; j < 2; j++) {
                ldsm4(bhi[j], bHi + (uint32_t)j * 16 * ROW_B + kb);
                ldsm4(blo[j], bLo + (uint32_t)j * 16 * ROW_B + kb);
            }
            #pragma unroll
            for (int i = 0; i < 4; i++) {
                #pragma unroll
                for (int n = 0; n < 4; n++) {
                    const uint32_t* bh = &bhi[n >> 1][(n & 1) * 2];
                    const uint32_t* bl = &blo[n >> 1][(n & 1) * 2];
                    mma_bf16(acc[i][n], ahi[i], bh);
                    mma_bf16(acc[i][n], ahi[i], bl);
                    mma_bf16(acc[i][n], alo[i], bh);
                }
            }
        }
        __syncthreads();
    }

    // Epilogue: scatter accumulators + bias
    const int trow = lid >> 2;        // 0..7
    const int tcol = (lid & 3) * 2;   // 0,2,4,6
    #pragma unroll
    for (int i = 0; i < 4; i++) {
        const int r0 = m0 + wm * 64 + i * 16 + trow;
        #pragma unroll
        for (int n = 0; n < 4; n++) {
            const int col = n0 + wn * 32 + n * 8 + tcol;
            const float b0 = bias[col], b1 = bias[col + 1];
            float2 v0, v1;
            v0.x = acc[i][n][0] + b0;  v0.y = acc[i][n][1] + b1;
            v1.x = acc[i][n][2] + b0;  v1.y = acc[i][n][3] + b1;
            *(float2*)&C[(size_t)r0 * N + col]       = v0;
            *(float2*)&C[(size_t)(r0 + 8) * N + col] = v1;
        }
    }
}

// ---------------------------------------------------------------------------
// Flash attention (causal, fp32) — unchanged (next round's target).
// ---------------------------------------------------------------------------
__global__ __launch_bounds__(64) void flash_attn_fp32(
    const float* __restrict__ qkv, float* __restrict__ out)
{
    __shared__ float Ks[32][64];
    __shared__ float Vs[32][64];

    const int tid = threadIdx.x;
    const int bh  = blockIdx.y;
    const int b   = bh >> 4;
    const int h   = bh & 15;
    const int qblk = (int)gridDim.x - 1 - (int)blockIdx.x;
    const int q0   = qblk * 64;
    const int row  = q0 + tid;

    const float SCALE = 0.125f;

    const float* qrow = qkv + (size_t)(b * TT + row) * (3 * CC) + h * HD;
    float q[HD];
    #pragma unroll
    for (int k = 0; k < HD; k += 4) {
        float4 v = *(const float4*)(qrow + k);
        q[k + 0] = v.x * SCALE;
        q[k + 1] = v.y * SCALE;
        q[k + 2] = v.z * SCALE;
        q[k + 3] = v.w * SCALE;
    }

    float o[HD];
    #pragma unroll
    for (int k = 0; k < HD; k++) o[k] = 0.0f;
    float mi = -__int_as_float(0x7f800000);
    float li = 0.0f;

    const int ntiles = (q0 + 64) / 32;

    for (int t = 0; t < ntiles; t++) {
        const int s0 = t * 32;
        const float* kbase = qkv + (size_t)(b * TT + s0) * (3 * CC) + CC + h * HD;
        const float* vbase = kbase + CC;
        #pragma unroll
        for (int j = 0; j < 8; j++) {
            const int idx4 = tid + j * 64;
            const int r = idx4 >> 4;
            const int c = (idx4 & 15) * 4;
            *(float4*)&Ks[r][c] = *(const float4*)(kbase + (size_t)r * (3 * CC) + c);
            *(float4*)&Vs[r][c] = *(const float4*)(vbase + (size_t)r * (3 * CC) + c);
        }
        __syncthreads();

        float s[32];
        #pragma unroll
        for (int j = 0; j < 32; j++) {
            float a = 0.0f;
            #pragma unroll
            for (int k = 0; k < HD; k += 4) {
                float4 kv = *(const float4*)&Ks[j][k];
                a += q[k]     * kv.x;
                a += q[k + 1] * kv.y;
                a += q[k + 2] * kv.z;
                a += q[k + 3] * kv.w;
            }
            s[j] = (s0 + j <= row) ? a : -__int_as_float(0x7f800000);
        }

        float mt = mi;
        #pragma unroll
        for (int j = 0; j < 32; j++) mt = fmaxf(mt, s[j]);
        const float rescale = __expf(mi - mt);
        li *= rescale;
        #pragma unroll
        for (int k = 0; k < HD; k++) o[k] *= rescale;

        float psum = 0.0f;
        #pragma unroll
        for (int j = 0; j < 32; j++) {
            const float p = __expf(s[j] - mt);
            s[j] = p;
            psum += p;
        }
        li += psum;
        mi = mt;

        #pragma unroll
        for (int j = 0; j < 32; j++) {
            const float p = s[j];
            #pragma unroll
            for (int k = 0; k < HD; k += 4) {
                float4 vv = *(const float4*)&Vs[j][k];
                o[k + 0] += p * vv.x;
                o[k + 1] += p * vv.y;
                o[k + 2] += p * vv.z;
                o[k + 3] += p * vv.w;
            }
        }
        __syncthreads();
    }

    const float inv = 1.0f / li;
    float* orow = out + (size_t)(b * TT + row) * CC + h * HD;
    #pragma unroll
    for (int k = 0; k < HD; k += 4) {
        float4 v;
        v.x = o[k + 0] * inv;
        v.y = o[k + 1] * inv;
        v.z = o[k + 2] * inv;
        v.w = o[k + 3] * inv;
        *(float4*)(orow + k) = v;
    }
}

// ---------------------------------------------------------------------------
extern "C" void kernel_launch(void* const* d_in, const int* in_sizes, int n_in,
                              void* d_out, int out_size)
{
    const float* x      = (const float*)d_in[0];
    const float* W_qkv  = (const float*)d_in[1];
    const float* b_qkv  = (const float*)d_in[2];
    const float* W_proj = (const float*)d_in[3];
    const float* b_proj = (const float*)d_in[4];
    float* out = (float*)d_out;

    float *qkv_ptr, *att_ptr;
    __nv_bfloat16 *xhi, *xlo, *wqh, *wql, *wph, *wpl, *ahi, *alo;
    cudaGetSymbolAddress((void**)&qkv_ptr, g_qkv);
    cudaGetSymbolAddress((void**)&att_ptr, g_att);
    cudaGetSymbolAddress((void**)&xhi, g_x_hi);
    cudaGetSymbolAddress((void**)&xlo, g_x_lo);
    cudaGetSymbolAddress((void**)&wqh, g_wqkv_hi);
    cudaGetSymbolAddress((void**)&wql, g_wqkv_lo);
    cudaGetSymbolAddress((void**)&wph, g_wproj_hi);
    cudaGetSymbolAddress((void**)&wpl, g_wproj_lo);
    cudaGetSymbolAddress((void**)&ahi, g_att_hi);
    cudaGetSymbolAddress((void**)&alo, g_att_lo);

    static bool attr_set = false;
    if (!attr_set) {
        cudaFuncSetAttribute(gemm_bf16x3_mma,
                             cudaFuncAttributeMaxDynamicSharedMemorySize, GEMM_SMEM);
        attr_set = true;
    }

    // 0) fp32 -> bf16 hi/lo splits
    {
        int n4 = (MROWS * CC) / 4;
        split_bf16_kernel<<<n4 / 256, 256>>>(x, xhi, xlo, n4);
        n4 = (3 * CC * CC) / 4;
        split_bf16_kernel<<<n4 / 256, 256>>>(W_qkv, wqh, wql, n4);
        n4 = (CC * CC) / 4;
        split_bf16_kernel<<<n4 / 256, 256>>>(W_proj, wph, wpl, n4);
    }

    // 1) QKV projection: [8192,1024] @ [3072,1024]^T + b -> [8192,3072]
    {
        dim3 grid((3 * CC) / 128, MROWS / 128);   // (24, 64)
        gemm_bf16x3_mma<<<grid, 256, GEMM_SMEM>>>(xhi, xlo, wqh, wql, b_qkv, qkv_ptr, CC, 3 * CC);
    }

    // 2) Causal flash attention -> g_att [8192,1024]
    {
        dim3 grid(TT / 64, BB * NH);              // (32, 64)
        flash_attn_fp32<<<grid, 64>>>(qkv_ptr, att_ptr);
    }

    // 3) split attention output, then output projection
    {
        int n4 = (MROWS * CC) / 4;
        split_bf16_kernel<<<n4 / 256, 256>>>(att_ptr, ahi, alo, n4);
        dim3 grid(CC / 128, MROWS / 128);         // (8, 64)
        gemm_bf16x3_mma<<<grid, 256, GEMM_SMEM>>>(ahi, alo, wph, wpl, b_proj, out, CC, CC);
    }
}

// round 4
// speedup vs baseline: 3.4631x; 2.5052x over previous
#include <cuda_runtime.h>
#include <cuda_bf16.h>
#include <cstdint>

// Problem constants
#define BB 4
#define TT 2048
#define CC 1024
#define NH 16
#define HD 64
#define MROWS (BB * TT)   // 8192

// ---------------------------------------------------------------------------
// Scratch (device globals — no cudaMalloc allowed)
// ---------------------------------------------------------------------------
__device__ float g_qkv[(size_t)MROWS * 3 * CC];            // [8192, 3072] fp32
__device__ float g_att[(size_t)MROWS * CC];                // [8192, 1024] fp32
__device__ __nv_bfloat16 g_x_hi[(size_t)MROWS * CC];
__device__ __nv_bfloat16 g_x_lo[(size_t)MROWS * CC];
__device__ __nv_bfloat16 g_wqkv_hi[(size_t)3 * CC * CC];
__device__ __nv_bfloat16 g_wqkv_lo[(size_t)3 * CC * CC];
__device__ __nv_bfloat16 g_wproj_hi[(size_t)CC * CC];
__device__ __nv_bfloat16 g_wproj_lo[(size_t)CC * CC];
__device__ __nv_bfloat16 g_att_hi[(size_t)MROWS * CC];
__device__ __nv_bfloat16 g_att_lo[(size_t)MROWS * CC];
__device__ __nv_bfloat16 g_qkv_hi[(size_t)MROWS * 3 * CC];
__device__ __nv_bfloat16 g_qkv_lo[(size_t)MROWS * 3 * CC];

// ---------------------------------------------------------------------------
// Helpers
// ---------------------------------------------------------------------------
__device__ __forceinline__ uint32_t smem_to_u32(const void* p) {
    uint32_t a;
    asm("{ .reg .u64 t; cvta.to.shared.u64 t, %1; cvt.u32.u64 %0, t; }" : "=r"(a) : "l"(p));
    return a;
}

#define CP_ASYNC_16(dst_u32, src_ptr) \
    asm volatile("cp.async.cg.shared.global [%0], [%1], 16;" \
        :: "r"(dst_u32), "l"(src_ptr) : "memory")
#define CP_ASYNC_COMMIT() asm volatile("cp.async.commit_group;" ::: "memory")
#define CP_ASYNC_WAIT(n)  asm volatile("cp.async.wait_group %0;" :: "n"(n) : "memory")

__device__ __forceinline__ void ldsm4(uint32_t* r, uint32_t addr) {
    asm volatile("ldmatrix.sync.aligned.m8n8.x4.shared.b16 {%0,%1,%2,%3}, [%4];"
        : "=r"(r[0]), "=r"(r[1]), "=r"(r[2]), "=r"(r[3]) : "r"(addr));
}
__device__ __forceinline__ void ldsm4t(uint32_t* r, uint32_t addr) {
    asm volatile("ldmatrix.sync.aligned.m8n8.x4.trans.shared.b16 {%0,%1,%2,%3}, [%4];"
        : "=r"(r[0]), "=r"(r[1]), "=r"(r[2]), "=r"(r[3]) : "r"(addr));
}

__device__ __forceinline__ void mma_bf16(float* c, const uint32_t* a, const uint32_t* b) {
    asm volatile(
        "mma.sync.aligned.m16n8k16.row.col.f32.bf16.bf16.f32 "
        "{%0,%1,%2,%3}, {%4,%5,%6,%7}, {%8,%9}, {%0,%1,%2,%3};"
        : "+f"(c[0]), "+f"(c[1]), "+f"(c[2]), "+f"(c[3])
        : "r"(a[0]), "r"(a[1]), "r"(a[2]), "r"(a[3]), "r"(b[0]), "r"(b[1]));
}

__device__ __forceinline__ uint32_t pack_bf16(float x, float y) {
    __nv_bfloat162 h = __float22bfloat162_rn(make_float2(x, y));
    return *(uint32_t*)&h;
}

// ---------------------------------------------------------------------------
// fp32 -> (bf16 hi, bf16 lo) split.
// ---------------------------------------------------------------------------
__global__ __launch_bounds__(256) void split_bf16_kernel(
    const float* __restrict__ in,
    __nv_bfloat16* __restrict__ hi, __nv_bfloat16* __restrict__ lo, int n4)
{
    int i = blockIdx.x * blockDim.x + threadIdx.x;
    if (i >= n4) return;
    float4 v = ((const float4*)in)[i];
    __nv_bfloat16 h0 = __float2bfloat16(v.x);
    __nv_bfloat16 h1 = __float2bfloat16(v.y);
    __nv_bfloat16 h2 = __float2bfloat16(v.z);
    __nv_bfloat16 h3 = __float2bfloat16(v.w);
    __nv_bfloat16 l0 = __float2bfloat16(v.x - __bfloat162float(h0));
    __nv_bfloat16 l1 = __float2bfloat16(v.y - __bfloat162float(h1));
    __nv_bfloat16 l2 = __float2bfloat16(v.z - __bfloat162float(h2));
    __nv_bfloat16 l3 = __float2bfloat16(v.w - __bfloat162float(h3));
    __nv_bfloat162 hA; hA.x = h0; hA.y = h1;
    __nv_bfloat162 hB; hB.x = h2; hB.y = h3;
    __nv_bfloat162 lA; lA.x = l0; lA.y = l1;
    __nv_bfloat162 lB; lB.x = l2; lB.y = l3;
    ((__nv_bfloat162*)hi)[2 * i]     = hA;
    ((__nv_bfloat162*)hi)[2 * i + 1] = hB;
    ((__nv_bfloat162*)lo)[2 * i]     = lA;
    ((__nv_bfloat162*)lo)[2 * i + 1] = lB;
}

// ---------------------------------------------------------------------------
// bf16x3 GEMM via mma.sync (unchanged from round 3).
// ---------------------------------------------------------------------------
#define ROW_B   80
#define TILE_B  (128 * ROW_B)
#define STAGE_B (4 * TILE_B)
#define GEMM_SMEM (2 * STAGE_B)

__global__ __launch_bounds__(256) void gemm_bf16x3_mma(
    const __nv_bfloat16* __restrict__ Ahi, const __nv_bfloat16* __restrict__ Alo,
    const __nv_bfloat16* __restrict__ Bhi, const __nv_bfloat16* __restrict__ Blo,
    const float* __restrict__ bias, float* __restrict__ C,
    int K, int N)
{
    extern __shared__ __align__(16) char smem[];
    const uint32_t sbase = smem_to_u32(smem);
    const int tid = threadIdx.x;
    const int wid = tid >> 5;
    const int lid = tid & 31;
    const int wm  = wid & 1;
    const int wn  = wid >> 1;
    const int m0  = blockIdx.y * 128;
    const int n0  = blockIdx.x * 128;

    const int lr = tid >> 2;
    const int cc = tid & 3;
    const uint32_t sm_off = (uint32_t)lr * ROW_B + (uint32_t)cc * 16;
    const int gcol = cc * 8;

    const uint32_t a_off = (uint32_t)(wm * 64 + (lid & 15)) * ROW_B + (uint32_t)(lid >> 4) * 16;
    const uint32_t b_off = (uint32_t)(wn * 32 + ((lid >> 4) << 3) + (lid & 7)) * ROW_B
                         + (uint32_t)((lid >> 3) & 1) * 16;

    float acc[4][4][4];
    #pragma unroll
    for (int i = 0; i < 4; i++)
        #pragma unroll
        for (int n = 0; n < 4; n++)
            #pragma unroll
            for (int v = 0; v < 4; v++)
                acc[i][n][v] = 0.0f;

    const int NCHUNK = K >> 5;

    auto load_stage = [&](int s, int k0) {
        const uint32_t st = sbase + (uint32_t)s * STAGE_B;
        const size_t ga = (size_t)(m0 + lr) * K + k0 + gcol;
        const size_t gb = (size_t)(n0 + lr) * K + k0 + gcol;
        CP_ASYNC_16(st + sm_off,                          Ahi + ga);
        CP_ASYNC_16(st + sm_off + 64u * ROW_B,            Ahi + ga + (size_t)64 * K);
        CP_ASYNC_16(st + TILE_B + sm_off,                 Alo + ga);
        CP_ASYNC_16(st + TILE_B + sm_off + 64u * ROW_B,   Alo + ga + (size_t)64 * K);
        CP_ASYNC_16(st + 2u * TILE_B + sm_off,                        Bhi + gb);
        CP_ASYNC_16(st + 2u * TILE_B + sm_off + 64u * ROW_B,          Bhi + gb + (size_t)64 * K);
        CP_ASYNC_16(st + 3u * TILE_B + sm_off,                        Blo + gb);
        CP_ASYNC_16(st + 3u * TILE_B + sm_off + 64u * ROW_B,          Blo + gb + (size_t)64 * K);
    };

    load_stage(0, 0);
    CP_ASYNC_COMMIT();

    for (int c = 0; c < NCHUNK; c++) {
        if (c + 1 < NCHUNK) {
            load_stage((c + 1) & 1, (c + 1) << 5);
            CP_ASYNC_COMMIT();
            CP_ASYNC_WAIT(1);
        } else {
            CP_ASYNC_WAIT(0);
        }
        __syncthreads();

        const uint32_t st  = sbase + (uint32_t)(c & 1) * STAGE_B;
        const uint32_t aHi = st + a_off;
        const uint32_t aLo = st + TILE_B + a_off;
        const uint32_t bHi = st + 2u * TILE_B + b_off;
        const uint32_t bLo = st + 3u * TILE_B + b_off;

        #pragma unroll
        for (int kk = 0; kk < 2; kk++) {
            const uint32_t kb = (uint32_t)kk * 32;
            uint32_t ahi[4][4], alo[4][4];
            #pragma unroll
            for (int i = 0; i < 4; i++) {
                ldsm4(ahi[i], aHi + (uint32_t)i * 16 * ROW_B + kb);
                ldsm4(alo[i], aLo + (uint32_t)i * 16 * ROW_B + kb);
            }
            uint32_t bhi[2][4], blo[2][4];
            #pragma unroll
            for (int j = 0; j < 2; j++) {
                ldsm4(bhi[j], bHi + (uint32_t)j * 16 * ROW_B + kb);
                ldsm4(blo[j], bLo + (uint32_t)j * 16 * ROW_B + kb);
            }
            #pragma unroll
            for (int i = 0; i < 4; i++) {
                #pragma unroll
                for (int n = 0; n < 4; n++) {
                    const uint32_t* bh = &bhi[n >> 1][(n & 1) * 2];
                    const uint32_t* bl = &blo[n >> 1][(n & 1) * 2];
                    mma_bf16(acc[i][n], ahi[i], bh);
                    mma_bf16(acc[i][n], ahi[i], bl);
                    mma_bf16(acc[i][n], alo[i], bh);
                }
            }
        }
        __syncthreads();
    }

    const int trow = lid >> 2;
    const int tcol = (lid & 3) * 2;
    #pragma unroll
    for (int i = 0; i < 4; i++) {
        const int r0 = m0 + wm * 64 + i * 16 + trow;
        #pragma unroll
        for (int n = 0; n < 4; n++) {
            const int col = n0 + wn * 32 + n * 8 + tcol;
            const float b0 = bias[col], b1 = bias[col + 1];
            float2 v0, v1;
            v0.x = acc[i][n][0] + b0;  v0.y = acc[i][n][1] + b1;
            v1.x = acc[i][n][2] + b0;  v1.y = acc[i][n][3] + b1;
            *(float2*)&C[(size_t)r0 * N + col]       = v0;
            *(float2*)&C[(size_t)(r0 + 8) * N + col] = v1;
        }
    }
}

// ---------------------------------------------------------------------------
// Tensor-core flash attention (causal, bf16x3 Ootomo).
// CTA: 128 q-rows of one (b,h). 8 warps, warp = m16 x n64.
// KV tiles of 64 rows, cp.async double-buffered.
// SMEM rows padded to 144B (64 bf16 + 8 pad) -> conflict-free ldmatrix.
// ---------------------------------------------------------------------------
#define AROW 144                      // bytes per smem row (64 bf16 + pad)
#define QT_B  (128 * AROW)            // 18432: one Q tile (hi or lo)
#define KVSUB (64 * AROW)             // 9216: one K or V sub-tile
#define KVSTG (4 * KVSUB)             // 36864: khi,klo,vhi,vlo
#define ATT_SMEM (2 * QT_B + 2 * KVSTG)   // 110592

__global__ __launch_bounds__(256, 1) void flash_attn_mma(
    const __nv_bfloat16* __restrict__ Qhi, const __nv_bfloat16* __restrict__ Qlo,
    float* __restrict__ out)
{
    extern __shared__ __align__(16) char smem[];
    const uint32_t sbase = smem_to_u32(smem);
    const int tid = threadIdx.x;
    const int wid = tid >> 5;
    const int lid = tid & 31;
    const int bh  = blockIdx.y;
    const int b   = bh >> 4;
    const int h   = bh & 15;
    const int qblk = (int)gridDim.x - 1 - (int)blockIdx.x;   // heavy first
    const int q0   = qblk * 128;
    const int nkv  = 2 * qblk + 2;     // kv tiles of 64 rows, covers [0, q0+128)

    const uint32_t qhi_s = sbase;
    const uint32_t qlo_s = sbase + QT_B;
    const uint32_t kv_s  = sbase + 2 * QT_B;

    // ---- cp.async loaders ----
    // Q: 2 arrays x 128 rows x 8 chunks = 2048 / 256 threads = 8 each
    {
        #pragma unroll
        for (int t = 0; t < 8; t++) {
            const int idx = tid + t * 256;
            const int arr = idx >> 10;           // 0=hi, 1=lo
            const int rem = idx & 1023;
            const int row = rem >> 3;
            const int ch  = rem & 7;
            const __nv_bfloat16* src = (arr ? Qlo : Qhi)
                + (size_t)(b * TT + q0 + row) * (3 * CC) + h * HD + ch * 8;
            CP_ASYNC_16(sbase + (uint32_t)arr * QT_B + (uint32_t)row * AROW + (uint32_t)ch * 16, src);
        }
    }
    auto load_kv = [&](int stage, int kv0) {
        const uint32_t st = kv_s + (uint32_t)stage * KVSTG;
        #pragma unroll
        for (int t = 0; t < 8; t++) {
            const int idx = tid + t * 256;
            const int arr = idx >> 9;            // 0:khi 1:klo 2:vhi 3:vlo
            const int rem = idx & 511;
            const int row = rem >> 3;
            const int ch  = rem & 7;
            const int colbase = ((arr >> 1) ? 2 * CC : CC) + h * HD;   // K at +1024, V at +2048
            const __nv_bfloat16* src = ((arr & 1) ? Qlo : Qhi)
                + (size_t)(b * TT + kv0 + row) * (3 * CC) + colbase + ch * 8;
            CP_ASYNC_16(st + (uint32_t)arr * KVSUB + (uint32_t)row * AROW + (uint32_t)ch * 16, src);
        }
    };

    load_kv(0, 0);
    CP_ASYNC_COMMIT();             // group: Q + kv tile 0
    load_kv(1, 64);
    CP_ASYNC_COMMIT();             // group: kv tile 1  (nkv >= 2 always)

    // ldmatrix lane offsets
    const uint32_t a_off = (uint32_t)(wid * 16 + (lid & 15)) * AROW + (uint32_t)(lid >> 4) * 16;
    const uint32_t k_off = (uint32_t)(((lid >> 4) << 3) + (lid & 7)) * AROW + (uint32_t)((lid >> 3) & 1) * 16;
    const uint32_t v_off = (uint32_t)(lid & 15) * AROW + (uint32_t)(lid >> 4) * 16;

    // state
    uint32_t qh[4][4], ql[4][4];
    float o[8][4];
    #pragma unroll
    for (int n = 0; n < 8; n++)
        #pragma unroll
        for (int v = 0; v < 4; v++) o[n][v] = 0.0f;
    float mi0 = -__int_as_float(0x7f800000), mi1 = mi0;
    float li0 = 0.0f, li1 = 0.0f;

    const int r_lo = wid * 16 + (lid >> 2);       // local row of c0/c1
    const int grow0 = q0 + r_lo;                  // global q row
    const int grow1 = grow0 + 8;
    const float NEG_INF = -__int_as_float(0x7f800000);

    for (int t = 0; t < nkv; t++) {
        if (t + 1 < nkv) CP_ASYNC_WAIT(1); else CP_ASYNC_WAIT(0);
        __syncthreads();

        if (t == 0) {
            // hoist Q fragments (valid after first wait)
            #pragma unroll
            for (int kk = 0; kk < 4; kk++) {
                ldsm4(qh[kk], qhi_s + a_off + (uint32_t)kk * 32);
                ldsm4(ql[kk], qlo_s + a_off + (uint32_t)kk * 32);
            }
        }

        const int kv0 = t * 64;
        const uint32_t st   = kv_s + (uint32_t)(t & 1) * KVSTG;
        const uint32_t khiB = st;
        const uint32_t kloB = st + KVSUB;
        const uint32_t vhiB = st + 2 * KVSUB;
        const uint32_t vloB = st + 3 * KVSUB;

        // ---- S = Q K^T (bf16x3) ----
        float s[8][4];
        #pragma unroll
        for (int n = 0; n < 8; n++)
            #pragma unroll
            for (int v = 0; v < 4; v++) s[n][v] = 0.0f;

        #pragma unroll
        for (int kk = 0; kk < 4; kk++) {
            const uint32_t kb = (uint32_t)kk * 32;
            uint32_t kh[4][4], kl[4][4];
            #pragma unroll
            for (int j = 0; j < 4; j++) {
                ldsm4(kh[j], khiB + k_off + (uint32_t)j * 16 * AROW + kb);
                ldsm4(kl[j], kloB + k_off + (uint32_t)j * 16 * AROW + kb);
            }
            #pragma unroll
            for (int n = 0; n < 8; n++) {
                const uint32_t* bh = &kh[n >> 1][(n & 1) * 2];
                const uint32_t* bl = &kl[n >> 1][(n & 1) * 2];
                mma_bf16(s[n], qh[kk], bh);
                mma_bf16(s[n], qh[kk], bl);
                mma_bf16(s[n], ql[kk], bh);
            }
        }

        // ---- scale + causal mask ----
        const bool need_mask = (kv0 + 63 > q0);
        #pragma unroll
        for (int n = 0; n < 8; n++) {
            #pragma unroll
            for (int v = 0; v < 4; v++) s[n][v] *= 0.125f;
            if (need_mask) {
                const int col = kv0 + n * 8 + (lid & 3) * 2;
                if (col > grow0)     s[n][0] = NEG_INF;
                if (col + 1 > grow0) s[n][1] = NEG_INF;
                if (col > grow1)     s[n][2] = NEG_INF;
                if (col + 1 > grow1) s[n][3] = NEG_INF;
            }
        }

        // ---- online softmax ----
        float mt0 = mi0, mt1 = mi1;
        #pragma unroll
        for (int n = 0; n < 8; n++) {
            mt0 = fmaxf(mt0, fmaxf(s[n][0], s[n][1]));
            mt1 = fmaxf(mt1, fmaxf(s[n][2], s[n][3]));
        }
        mt0 = fmaxf(mt0, __shfl_xor_sync(0xffffffffu, mt0, 1));
        mt0 = fmaxf(mt0, __shfl_xor_sync(0xffffffffu, mt0, 2));
        mt1 = fmaxf(mt1, __shfl_xor_sync(0xffffffffu, mt1, 1));
        mt1 = fmaxf(mt1, __shfl_xor_sync(0xffffffffu, mt1, 2));

        const float rs0 = __expf(mi0 - mt0);
        const float rs1 = __expf(mi1 - mt1);
        mi0 = mt0; mi1 = mt1;
        li0 *= rs0; li1 *= rs1;
        #pragma unroll
        for (int n = 0; n < 8; n++) {
            o[n][0] *= rs0; o[n][1] *= rs0;
            o[n][2] *= rs1; o[n][3] *= rs1;
        }

        uint32_t ph[4][4], pl[4][4];   // [kk][a-frag]
        #pragma unroll
        for (int n = 0; n < 8; n++) {
            float p0 = __expf(s[n][0] - mt0);
            float p1 = __expf(s[n][1] - mt0);
            float p2 = __expf(s[n][2] - mt1);
            float p3 = __expf(s[n][3] - mt1);
            li0 += p0 + p1;
            li1 += p2 + p3;
            const int kk = n >> 1;
            const int hi = (n & 1) * 2;          // a0/a1 for even n, a2/a3 for odd n
            uint32_t u01 = pack_bf16(p0, p1);
            uint32_t u23 = pack_bf16(p2, p3);
            ph[kk][hi]     = u01;
            ph[kk][hi + 1] = u23;
            __nv_bfloat162 h01 = *(__nv_bfloat162*)&u01;
            __nv_bfloat162 h23 = *(__nv_bfloat162*)&u23;
            pl[kk][hi]     = pack_bf16(p0 - __bfloat162float(h01.x), p1 - __bfloat162float(h01.y));
            pl[kk][hi + 1] = pack_bf16(p2 - __bfloat162float(h23.x), p3 - __bfloat162float(h23.y));
        }

        // ---- O += P V (bf16x3) ----
        #pragma unroll
        for (int kk = 0; kk < 4; kk++) {
            uint32_t vh[4][4], vl[4][4];
            #pragma unroll
            for (int jp = 0; jp < 4; jp++) {
                const uint32_t off = v_off + (uint32_t)kk * 16 * AROW + (uint32_t)jp * 32;
                ldsm4t(vh[jp], vhiB + off);
                ldsm4t(vl[jp], vloB + off);
            }
            #pragma unroll
            for (int n = 0; n < 8; n++) {
                const uint32_t* bh = &vh[n >> 1][(n & 1) * 2];
                const uint32_t* bl = &vl[n >> 1][(n & 1) * 2];
                mma_bf16(o[n], ph[kk], bh);
                mma_bf16(o[n], ph[kk], bl);
                mma_bf16(o[n], pl[kk], bh);
            }
        }

        __syncthreads();                       // stage reuse barrier
        if (t + 2 < nkv) {
            load_kv(t & 1, (t + 2) * 64);
            CP_ASYNC_COMMIT();
        }
    }

    // ---- finalize: reduce row sums across quad lanes, normalize, store ----
    li0 += __shfl_xor_sync(0xffffffffu, li0, 1);
    li0 += __shfl_xor_sync(0xffffffffu, li0, 2);
    li1 += __shfl_xor_sync(0xffffffffu, li1, 1);
    li1 += __shfl_xor_sync(0xffffffffu, li1, 2);
    const float inv0 = 1.0f / li0;
    const float inv1 = 1.0f / li1;

    #pragma unroll
    for (int n = 0; n < 8; n++) {
        const int gcol = h * HD + n * 8 + (lid & 3) * 2;
        float2 v0, v1;
        v0.x = o[n][0] * inv0;  v0.y = o[n][1] * inv0;
        v1.x = o[n][2] * inv1;  v1.y = o[n][3] * inv1;
        *(float2*)&out[(size_t)(b * TT + grow0) * CC + gcol] = v0;
        *(float2*)&out[(size_t)(b * TT + grow1) * CC + gcol] = v1;
    }
}

// ---------------------------------------------------------------------------
extern "C" void kernel_launch(void* const* d_in, const int* in_sizes, int n_in,
                              void* d_out, int out_size)
{
    const float* x      = (const float*)d_in[0];
    const float* W_qkv  = (const float*)d_in[1];
    const float* b_qkv  = (const float*)d_in[2];
    const float* W_proj = (const float*)d_in[3];
    const float* b_proj = (const float*)d_in[4];
    float* out = (float*)d_out;

    float *qkv_ptr, *att_ptr;
    __nv_bfloat16 *xhi, *xlo, *wqh, *wql, *wph, *wpl, *ahi, *alo, *qkvh, *qkvl;
    cudaGetSymbolAddress((void**)&qkv_ptr, g_qkv);
    cudaGetSymbolAddress((void**)&att_ptr, g_att);
    cudaGetSymbolAddress((void**)&xhi, g_x_hi);
    cudaGetSymbolAddress((void**)&xlo, g_x_lo);
    cudaGetSymbolAddress((void**)&wqh, g_wqkv_hi);
    cudaGetSymbolAddress((void**)&wql, g_wqkv_lo);
    cudaGetSymbolAddress((void**)&wph, g_wproj_hi);
    cudaGetSymbolAddress((void**)&wpl, g_wproj_lo);
    cudaGetSymbolAddress((void**)&ahi, g_att_hi);
    cudaGetSymbolAddress((void**)&alo, g_att_lo);
    cudaGetSymbolAddress((void**)&qkvh, g_qkv_hi);
    cudaGetSymbolAddress((void**)&qkvl, g_qkv_lo);

    static bool attr_set = false;
    if (!attr_set) {
        cudaFuncSetAttribute(gemm_bf16x3_mma,
                             cudaFuncAttributeMaxDynamicSharedMemorySize, GEMM_SMEM);
        cudaFuncSetAttribute(flash_attn_mma,
                             cudaFuncAttributeMaxDynamicSharedMemorySize, ATT_SMEM);
        attr_set = true;
    }

    // 0) fp32 -> bf16 hi/lo splits of inputs
    {
        int n4 = (MROWS * CC) / 4;
        split_bf16_kernel<<<n4 / 256, 256>>>(x, xhi, xlo, n4);
        n4 = (3 * CC * CC) / 4;
        split_bf16_kernel<<<n4 / 256, 256>>>(W_qkv, wqh, wql, n4);
        n4 = (CC * CC) / 4;
        split_bf16_kernel<<<n4 / 256, 256>>>(W_proj, wph, wpl, n4);
    }

    // 1) QKV projection: [8192,1024] @ [3072,1024]^T + b -> [8192,3072]
    {
        dim3 grid((3 * CC) / 128, MROWS / 128);
        gemm_bf16x3_mma<<<grid, 256, GEMM_SMEM>>>(xhi, xlo, wqh, wql, b_qkv, qkv_ptr, CC, 3 * CC);
    }

    // 1b) split qkv into bf16 hi/lo for the attention kernel
    {
        int n4 = (MROWS * 3 * CC) / 4;
        split_bf16_kernel<<<n4 / 256, 256>>>(qkv_ptr, qkvh, qkvl, n4);
    }

    // 2) Tensor-core causal flash attention -> g_att [8192,1024]
    {
        dim3 grid(TT / 128, BB * NH);            // (16, 64)
        flash_attn_mma<<<grid, 256, ATT_SMEM>>>(qkvh, qkvl, att_ptr);
    }

    // 3) split attention output, then output projection
    {
        int n4 = (MROWS * CC) / 4;
        split_bf16_kernel<<<n4 / 256, 256>>>(att_ptr, ahi, alo, n4);
        dim3 grid(CC / 128, MROWS / 128);
        gemm_bf16x3_mma<<<grid, 256, GEMM_SMEM>>>(ahi, alo, wph, wpl, b_proj, out, CC, CC);
    }
}

// round 7
// speedup vs baseline: 4.4181x; 1.2758x over previous
#include <cuda_runtime.h>
#include <cuda_fp16.h>
#include <cstdint>

// Problem constants
#define BB 4
#define TT 2048
#define CC 1024
#define NH 16
#define HD 64
#define MROWS (BB * TT)   // 8192

// ---------------------------------------------------------------------------
// Scratch (device globals — no cudaMalloc allowed)
// ---------------------------------------------------------------------------
__device__ __half g_x_hi[(size_t)MROWS * CC];
__device__ __half g_wqkv_hi[(size_t)3 * CC * CC];
__device__ __half g_wqkv_lo[(size_t)3 * CC * CC];
__device__ __half g_wproj_hi[(size_t)CC * CC];
__device__ __half g_wproj_lo[(size_t)CC * CC];
__device__ __half g_qkv_hi[(size_t)MROWS * 3 * CC];
__device__ __half g_qkv_lo[(size_t)MROWS * 3 * CC];
__device__ __half g_att_hi[(size_t)MROWS * CC];
__device__ __half g_att_lo[(size_t)MROWS * CC];

// ---------------------------------------------------------------------------
// Helpers
// ---------------------------------------------------------------------------
__device__ __forceinline__ uint32_t smem_to_u32(const void* p) {
    uint32_t a;
    asm("{ .reg .u64 t; cvta.to.shared.u64 t, %1; cvt.u32.u64 %0, t; }" : "=r"(a) : "l"(p));
    return a;
}

#define CP_ASYNC_16(dst_u32, src_ptr) \
    asm volatile("cp.async.cg.shared.global [%0], [%1], 16;" \
        :: "r"(dst_u32), "l"(src_ptr) : "memory")
#define CP_ASYNC_COMMIT() asm volatile("cp.async.commit_group;" ::: "memory")
#define CP_ASYNC_WAIT(n)  asm volatile("cp.async.wait_group %0;" :: "n"(n) : "memory")

__device__ __forceinline__ void ldsm4(uint32_t* r, uint32_t addr) {
    asm volatile("ldmatrix.sync.aligned.m8n8.x4.shared.b16 {%0,%1,%2,%3}, [%4];"
        : "=r"(r[0]), "=r"(r[1]), "=r"(r[2]), "=r"(r[3]) : "r"(addr));
}
__device__ __forceinline__ void ldsm4t(uint32_t* r, uint32_t addr) {
    asm volatile("ldmatrix.sync.aligned.m8n8.x4.trans.shared.b16 {%0,%1,%2,%3}, [%4];"
        : "=r"(r[0]), "=r"(r[1]), "=r"(r[2]), "=r"(r[3]) : "r"(addr));
}

__device__ __forceinline__ void mma_f16(float* c, const uint32_t* a, const uint32_t* b) {
    asm volatile(
        "mma.sync.aligned.m16n8k16.row.col.f32.f16.f16.f32 "
        "{%0,%1,%2,%3}, {%4,%5,%6,%7}, {%8,%9}, {%0,%1,%2,%3};"
        : "+f"(c[0]), "+f"(c[1]), "+f"(c[2]), "+f"(c[3])
        : "r"(a[0]), "r"(a[1]), "r"(a[2]), "r"(a[3]), "r"(b[0]), "r"(b[1]));
}

__device__ __forceinline__ uint32_t pack_half(float x, float y) {
    __half2 h = __floats2half2_rn(x, y);
    return *(uint32_t*)&h;
}

// ---------------------------------------------------------------------------
// fp32 -> fp16 convert (hi only)
// ---------------------------------------------------------------------------
__global__ __launch_bounds__(256) void tohalf_kernel(
    const float* __restrict__ in, __half* __restrict__ hi, int n4)
{
    int i = blockIdx.x * blockDim.x + threadIdx.x;
    if (i >= n4) return;
    float4 v = ((const float4*)in)[i];
    ((__half2*)hi)[2 * i]     = __floats2half2_rn(v.x, v.y);
    ((__half2*)hi)[2 * i + 1] = __floats2half2_rn(v.z, v.w);
}

// fp32 -> (fp16 hi, fp16 lo) split
__global__ __launch_bounds__(256) void split_half_kernel(
    const float* __restrict__ in,
    __half* __restrict__ hi, __half* __restrict__ lo, int n4)
{
    int i = blockIdx.x * blockDim.x + threadIdx.x;
    if (i >= n4) return;
    float4 v = ((const float4*)in)[i];
    __half h0 = __float2half_rn(v.x);
    __half h1 = __float2half_rn(v.y);
    __half h2 = __float2half_rn(v.z);
    __half h3 = __float2half_rn(v.w);
    __half2 hA; hA.x = h0; hA.y = h1;
    __half2 hB; hB.x = h2; hB.y = h3;
    ((__half2*)hi)[2 * i]     = hA;
    ((__half2*)hi)[2 * i + 1] = hB;
    __half2 lA = __floats2half2_rn(v.x - __half2float(h0), v.y - __half2float(h1));
    __half2 lB = __floats2half2_rn(v.z - __half2float(h2), v.w - __half2float(h3));
    ((__half2*)lo)[2 * i]     = lA;
    ((__half2*)lo)[2 * i + 1] = lB;
}

// ---------------------------------------------------------------------------
// fp16 Ootomo GEMM via mma.sync:  C[m,n] = sum_k A[m,k]*W[n,k] + bias[n]
// TERMS==2: acc = Ahi*Bhi + Ahi*Blo          (Alo unused)
// TERMS==3: acc += Alo*Bhi
// SPLIT: write fp16 hi/lo pair instead of fp32.
// CTA 128x128, BK=32, 8 warps (2m x 4n), cp.async 2-stage.
// ---------------------------------------------------------------------------
#define ROW_B   80
#define TILE_B  (128 * ROW_B)
#define STAGE_B (4 * TILE_B)
#define GEMM_SMEM (2 * STAGE_B)

template<int TERMS, bool SPLIT>
__global__ __launch_bounds__(256) void gemm_f16_mma(
    const __half* __restrict__ Ahi, const __half* __restrict__ Alo,
    const __half* __restrict__ Bhi, const __half* __restrict__ Blo,
    const float* __restrict__ bias,
    float* __restrict__ Cf, __half* __restrict__ Chi, __half* __restrict__ Clo,
    int K, int N)
{
    extern __shared__ __align__(16) char smem[];
    const uint32_t sbase = smem_to_u32(smem);
    const int tid = threadIdx.x;
    const int wid = tid >> 5;
    const int lid = tid & 31;
    const int wm  = wid & 1;
    const int wn  = wid >> 1;
    const int m0  = blockIdx.y * 128;
    const int n0  = blockIdx.x * 128;

    const int lr = tid >> 2;
    const int cc = tid & 3;
    const uint32_t sm_off = (uint32_t)lr * ROW_B + (uint32_t)cc * 16;
    const int gcol = cc * 8;

    const uint32_t a_off = (uint32_t)(wm * 64 + (lid & 15)) * ROW_B + (uint32_t)(lid >> 4) * 16;
    const uint32_t b_off = (uint32_t)(wn * 32 + ((lid >> 4) << 3) + (lid & 7)) * ROW_B
                         + (uint32_t)((lid >> 3) & 1) * 16;

    float acc[4][4][4];
    #pragma unroll
    for (int i = 0; i < 4; i++)
        #pragma unroll
        for (int n = 0; n < 4; n++)
            #pragma unroll
            for (int v = 0; v < 4; v++)
                acc[i][n][v] = 0.0f;

    const int NCHUNK = K >> 5;

    auto load_stage = [&](int s, int k0) {
        const uint32_t st = sbase + (uint32_t)s * STAGE_B;
        const size_t ga = (size_t)(m0 + lr) * K + k0 + gcol;
        const size_t gb = (size_t)(n0 + lr) * K + k0 + gcol;
        CP_ASYNC_16(st + sm_off,                          Ahi + ga);
        CP_ASYNC_16(st + sm_off + 64u * ROW_B,            Ahi + ga + (size_t)64 * K);
        if constexpr (TERMS == 3) {
            CP_ASYNC_16(st + TILE_B + sm_off,                 Alo + ga);
            CP_ASYNC_16(st + TILE_B + sm_off + 64u * ROW_B,   Alo + ga + (size_t)64 * K);
        }
        CP_ASYNC_16(st + 2u * TILE_B + sm_off,                        Bhi + gb);
        CP_ASYNC_16(st + 2u * TILE_B + sm_off + 64u * ROW_B,          Bhi + gb + (size_t)64 * K);
        CP_ASYNC_16(st + 3u * TILE_B + sm_off,                        Blo + gb);
        CP_ASYNC_16(st + 3u * TILE_B + sm_off + 64u * ROW_B,          Blo + gb + (size_t)64 * K);
    };

    load_stage(0, 0);
    CP_ASYNC_COMMIT();

    for (int c = 0; c < NCHUNK; c++) {
        if (c + 1 < NCHUNK) {
            load_stage((c + 1) & 1, (c + 1) << 5);
            CP_ASYNC_COMMIT();
            CP_ASYNC_WAIT(1);
        } else {
            CP_ASYNC_WAIT(0);
        }
        __syncthreads();

        const uint32_t st  = sbase + (uint32_t)(c & 1) * STAGE_B;
        const uint32_t aHi = st + a_off;
        const uint32_t aLo = st + TILE_B + a_off;
        const uint32_t bHi = st + 2u * TILE_B + b_off;
        const uint32_t bLo = st + 3u * TILE_B + b_off;

        #pragma unroll
        for (int kk = 0; kk < 2; kk++) {
            const uint32_t kb = (uint32_t)kk * 32;
            uint32_t ahi[4][4], alo[4][4];
            #pragma unroll
            for (int i = 0; i < 4; i++) {
                ldsm4(ahi[i], aHi + (uint32_t)i * 16 * ROW_B + kb);
                if constexpr (TERMS == 3)
                    ldsm4(alo[i], aLo + (uint32_t)i * 16 * ROW_B + kb);
            }
            uint32_t bhi[2][4], blo[2][4];
            #pragma unroll
            for (int j = 0; j < 2; j++) {
                ldsm4(bhi[j], bHi + (uint32_t)j * 16 * ROW_B + kb);
                ldsm4(blo[j], bLo + (uint32_t)j * 16 * ROW_B + kb);
            }
            #pragma unroll
            for (int i = 0; i < 4; i++) {
                #pragma unroll
                for (int n = 0; n < 4; n++) {
                    const uint32_t* bh = &bhi[n >> 1][(n & 1) * 2];
                    const uint32_t* bl = &blo[n >> 1][(n & 1) * 2];
                    mma_f16(acc[i][n], ahi[i], bh);
                    mma_f16(acc[i][n], ahi[i], bl);
                    if constexpr (TERMS == 3)
                        mma_f16(acc[i][n], alo[i], bh);
                }
            }
        }
        __syncthreads();
    }

    // Epilogue
    const int trow = lid >> 2;
    const int tcol = (lid & 3) * 2;
    #pragma unroll
    for (int i = 0; i < 4; i++) {
        const int r0 = m0 + wm * 64 + i * 16 + trow;
        #pragma unroll
        for (int n = 0; n < 4; n++) {
            const int col = n0 + wn * 32 + n * 8 + tcol;
            const float b0 = bias[col], b1 = bias[col + 1];
            float v00 = acc[i][n][0] + b0, v01 = acc[i][n][1] + b1;
            float v10 = acc[i][n][2] + b0, v11 = acc[i][n][3] + b1;
            if constexpr (SPLIT) {
                __half2 h0 = __floats2half2_rn(v00, v01);
                __half2 h1 = __floats2half2_rn(v10, v11);
                __half2 l0 = __floats2half2_rn(v00 - __half2float(h0.x), v01 - __half2float(h0.y));
                __half2 l1 = __floats2half2_rn(v10 - __half2float(h1.x), v11 - __half2float(h1.y));
                *(__half2*)&Chi[(size_t)r0 * N + col]       = h0;
                *(__half2*)&Chi[(size_t)(r0 + 8) * N + col] = h1;
                *(__half2*)&Clo[(size_t)r0 * N + col]       = l0;
                *(__half2*)&Clo[(size_t)(r0 + 8) * N + col] = l1;
            } else {
                float2 f0; f0.x = v00; f0.y = v01;
                float2 f1; f1.x = v10; f1.y = v11;
                *(float2*)&Cf[(size_t)r0 * N + col]       = f0;
                *(float2*)&Cf[(size_t)(r0 + 8) * N + col] = f1;
            }
        }
    }
}

// ---------------------------------------------------------------------------
// Tensor-core flash attention (causal, fp16 2-term Ootomo).
// CTA: 128 q-rows of one (b,h). 8 warps, warp = m16 x n64.
// S = Qhi*Khi + Qhi*Klo ;  O += Phi*Vhi + Phi*Vlo.
// Writes fp16 hi/lo output (for the 3-term proj GEMM).
// ---------------------------------------------------------------------------
#define AROW 144
#define QT_B  (128 * AROW)
#define KVSUB (64 * AROW)
#define KVSTG (4 * KVSUB)
#define ATT_SMEM (QT_B + 2 * KVSTG)   // 92160

__global__ __launch_bounds__(256, 1) void flash_attn_mma(
    const __half* __restrict__ Ghi, const __half* __restrict__ Glo,
    __half* __restrict__ Ohi, __half* __restrict__ Olo)
{
    extern __shared__ __align__(16) char smem[];
    const uint32_t sbase = smem_to_u32(smem);
    const int tid = threadIdx.x;
    const int wid = tid >> 5;
    const int lid = tid & 31;
    const int bh  = blockIdx.y;
    const int b   = bh >> 4;
    const int h   = bh & 15;
    const int qblk = (int)gridDim.x - 1 - (int)blockIdx.x;
    const int q0   = qblk * 128;
    const int nkv  = 2 * qblk + 2;

    const uint32_t qhi_s = sbase;
    const uint32_t kv_s  = sbase + QT_B;

    // Q hi tile: 128 rows x 8 chunks = 1024 / 256 threads = 4 each
    {
        #pragma unroll
        for (int t = 0; t < 4; t++) {
            const int idx = tid + t * 256;
            const int row = idx >> 3;
            const int ch  = idx & 7;
            const __half* src = Ghi + (size_t)(b * TT + q0 + row) * (3 * CC) + h * HD + ch * 8;
            CP_ASYNC_16(qhi_s + (uint32_t)row * AROW + (uint32_t)ch * 16, src);
        }
    }
    auto load_kv = [&](int stage, int kv0) {
        const uint32_t st = kv_s + (uint32_t)stage * KVSTG;
        #pragma unroll
        for (int t = 0; t < 8; t++) {
            const int idx = tid + t * 256;
            const int arr = idx >> 9;            // 0:khi 1:klo 2:vhi 3:vlo
            const int rem = idx & 511;
            const int row = rem >> 3;
            const int ch  = rem & 7;
            const int colbase = ((arr >> 1) ? 2 * CC : CC) + h * HD;
            const __half* src = ((arr & 1) ? Glo : Ghi)
                + (size_t)(b * TT + kv0 + row) * (3 * CC) + colbase + ch * 8;
            CP_ASYNC_16(st + (uint32_t)arr * KVSUB + (uint32_t)row * AROW + (uint32_t)ch * 16, src);
        }
    };

    load_kv(0, 0);
    CP_ASYNC_COMMIT();
    load_kv(1, 64);
    CP_ASYNC_COMMIT();

    const uint32_t a_off = (uint32_t)(wid * 16 + (lid & 15)) * AROW + (uint32_t)(lid >> 4) * 16;
    const uint32_t k_off = (uint32_t)(((lid >> 4) << 3) + (lid & 7)) * AROW + (uint32_t)((lid >> 3) & 1) * 16;
    const uint32_t v_off = (uint32_t)(lid & 15) * AROW + (uint32_t)(lid >> 4) * 16;

    uint32_t qh[4][4];
    float o[8][4];
    #pragma unroll
    for (int n = 0; n < 8; n++)
        #pragma unroll
        for (int v = 0; v < 4; v++) o[n][v] = 0.0f;
    float mi0 = -__int_as_float(0x7f800000), mi1 = mi0;
    float li0 = 0.0f, li1 = 0.0f;

    const int r_lo = wid * 16 + (lid >> 2);
    const int grow0 = q0 + r_lo;
    const int grow1 = grow0 + 8;
    const float NEG_INF = -__int_as_float(0x7f800000);

    for (int t = 0; t < nkv; t++) {
        if (t + 1 < nkv) CP_ASYNC_WAIT(1); else CP_ASYNC_WAIT(0);
        __syncthreads();

        if (t == 0) {
            #pragma unroll
            for (int kk = 0; kk < 4; kk++)
                ldsm4(qh[kk], qhi_s + a_off + (uint32_t)kk * 32);
        }

        const int kv0 = t * 64;
        const uint32_t st   = kv_s + (uint32_t)(t & 1) * KVSTG;
        const uint32_t khiB = st;
        const uint32_t kloB = st + KVSUB;
        const uint32_t vhiB = st + 2 * KVSUB;
        const uint32_t vloB = st + 3 * KVSUB;

        // ---- S = Q K^T (2-term) ----
        float s[8][4];
        #pragma unroll
        for (int n = 0; n < 8; n++)
            #pragma unroll
            for (int v = 0; v < 4; v++) s[n][v] = 0.0f;

        #pragma unroll
        for (int kk = 0; kk < 4; kk++) {
            const uint32_t kb = (uint32_t)kk * 32;
            uint32_t kh[4][4], kl[4][4];
            #pragma unroll
            for (int j = 0; j < 4; j++) {
                ldsm4(kh[j], khiB + k_off + (uint32_t)j * 16 * AROW + kb);
                ldsm4(kl[j], kloB + k_off + (uint32_t)j * 16 * AROW + kb);
            }
            #pragma unroll
            for (int n = 0; n < 8; n++) {
                const uint32_t* bh = &kh[n >> 1][(n & 1) * 2];
                const uint32_t* bl = &kl[n >> 1][(n & 1) * 2];
                mma_f16(s[n], qh[kk], bh);
                mma_f16(s[n], qh[kk], bl);
            }
        }

        // ---- scale + causal mask ----
        const bool need_mask = (kv0 + 63 > q0);
        #pragma unroll
        for (int n = 0; n < 8; n++) {
            #pragma unroll
            for (int v = 0; v < 4; v++) s[n][v] *= 0.125f;
            if (need_mask) {
                const int col = kv0 + n * 8 + (lid & 3) * 2;
                if (col > grow0)     s[n][0] = NEG_INF;
                if (col + 1 > grow0) s[n][1] = NEG_INF;
                if (col > grow1)     s[n][2] = NEG_INF;
                if (col + 1 > grow1) s[n][3] = NEG_INF;
            }
        }

        // ---- online softmax ----
        float mt0 = mi0, mt1 = mi1;
        #pragma unroll
        for (int n = 0; n < 8; n++) {
            mt0 = fmaxf(mt0, fmaxf(s[n][0], s[n][1]));
            mt1 = fmaxf(mt1, fmaxf(s[n][2], s[n][3]));
        }
        mt0 = fmaxf(mt0, __shfl_xor_sync(0xffffffffu, mt0, 1));
        mt0 = fmaxf(mt0, __shfl_xor_sync(0xffffffffu, mt0, 2));
        mt1 = fmaxf(mt1, __shfl_xor_sync(0xffffffffu, mt1, 1));
        mt1 = fmaxf(mt1, __shfl_xor_sync(0xffffffffu, mt1, 2));

        const float rs0 = __expf(mi0 - mt0);
        const float rs1 = __expf(mi1 - mt1);
        mi0 = mt0; mi1 = mt1;
        li0 *= rs0; li1 *= rs1;
        #pragma unroll
        for (int n = 0; n < 8; n++) {
            o[n][0] *= rs0; o[n][1] *= rs0;
            o[n][2] *= rs1; o[n][3] *= rs1;
        }

        uint32_t ph[4][4];
        #pragma unroll
        for (int n = 0; n < 8; n++) {
            float p0 = __expf(s[n][0] - mt0);
            float p1 = __expf(s[n][1] - mt0);
            float p2 = __expf(s[n][2] - mt1);
            float p3 = __expf(s[n][3] - mt1);
            li0 += p0 + p1;
            li1 += p2 + p3;
            const int kk = n >> 1;
            const int hi = (n & 1) * 2;
            ph[kk][hi]     = pack_half(p0, p1);
            ph[kk][hi + 1] = pack_half(p2, p3);
        }

        // ---- O += P V (2-term) ----
        #pragma unroll
        for (int kk = 0; kk < 4; kk++) {
            uint32_t vh[4][4], vl[4][4];
            #pragma unroll
            for (int jp = 0; jp < 4; jp++) {
                const uint32_t off = v_off + (uint32_t)kk * 16 * AROW + (uint32_t)jp * 32;
                ldsm4t(vh[jp], vhiB + off);
                ldsm4t(vl[jp], vloB + off);
            }
            #pragma unroll
            for (int n = 0; n < 8; n++) {
                const uint32_t* bh = &vh[n >> 1][(n & 1) * 2];
                const uint32_t* bl = &vl[n >> 1][(n & 1) * 2];
                mma_f16(o[n], ph[kk], bh);
                mma_f16(o[n], ph[kk], bl);
            }
        }

        __syncthreads();
        if (t + 2 < nkv) {
            load_kv(t & 1, (t + 2) * 64);
            CP_ASYNC_COMMIT();
        }
    }

    // ---- finalize ----
    li0 += __shfl_xor_sync(0xffffffffu, li0, 1);
    li0 += __shfl_xor_sync(0xffffffffu, li0, 2);
    li1 += __shfl_xor_sync(0xffffffffu, li1, 1);
    li1 += __shfl_xor_sync(0xffffffffu, li1, 2);
    const float inv0 = 1.0f / li0;
    const float inv1 = 1.0f / li1;

    #pragma unroll
    for (int n = 0; n < 8; n++) {
        const int gcol = h * HD + n * 8 + (lid & 3) * 2;
        float v00 = o[n][0] * inv0, v01 = o[n][1] * inv0;
        float v10 = o[n][2] * inv1, v11 = o[n][3] * inv1;
        __half2 h0 = __floats2half2_rn(v00, v01);
        __half2 h1 = __floats2half2_rn(v10, v11);
        __half2 l0 = __floats2half2_rn(v00 - __half2float(h0.x), v01 - __half2float(h0.y));
        __half2 l1 = __floats2half2_rn(v10 - __half2float(h1.x), v11 - __half2float(h1.y));
        *(__half2*)&Ohi[(size_t)(b * TT + grow0) * CC + gcol] = h0;
        *(__half2*)&Ohi[(size_t)(b * TT + grow1) * CC + gcol] = h1;
        *(__half2*)&Olo[(size_t)(b * TT + grow0) * CC + gcol] = l0;
        *(__half2*)&Olo[(size_t)(b * TT + grow1) * CC + gcol] = l1;
    }
}

// ---------------------------------------------------------------------------
extern "C" void kernel_launch(void* const* d_in, const int* in_sizes, int n_in,
                              void* d_out, int out_size)
{
    const float* x      = (const float*)d_in[0];
    const float* W_qkv  = (const float*)d_in[1];
    const float* b_qkv  = (const float*)d_in[2];
    const float* W_proj = (const float*)d_in[3];
    const float* b_proj = (const float*)d_in[4];
    float* out = (float*)d_out;

    __half *xhi, *wqh, *wql, *wph, *wpl, *qkvh, *qkvl, *atth, *attl;
    cudaGetSymbolAddress((void**)&xhi,  g_x_hi);
    cudaGetSymbolAddress((void**)&wqh,  g_wqkv_hi);
    cudaGetSymbolAddress((void**)&wql,  g_wqkv_lo);
    cudaGetSymbolAddress((void**)&wph,  g_wproj_hi);
    cudaGetSymbolAddress((void**)&wpl,  g_wproj_lo);
    cudaGetSymbolAddress((void**)&qkvh, g_qkv_hi);
    cudaGetSymbolAddress((void**)&qkvl, g_qkv_lo);
    cudaGetSymbolAddress((void**)&atth, g_att_hi);
    cudaGetSymbolAddress((void**)&attl, g_att_lo);

    static bool attr_set = false;
    if (!attr_set) {
        cudaFuncSetAttribute(gemm_f16_mma<2, true>,
                             cudaFuncAttributeMaxDynamicSharedMemorySize, GEMM_SMEM);
        cudaFuncSetAttribute(gemm_f16_mma<3, false>,
                             cudaFuncAttributeMaxDynamicSharedMemorySize, GEMM_SMEM);
        cudaFuncSetAttribute(flash_attn_mma,
                             cudaFuncAttributeMaxDynamicSharedMemorySize, ATT_SMEM);
        attr_set = true;
    }

    // 0) input conversions
    {
        int n4 = (MROWS * CC) / 4;
        tohalf_kernel<<<n4 / 256, 256>>>(x, xhi, n4);
        n4 = (3 * CC * CC) / 4;
        split_half_kernel<<<n4 / 256, 256>>>(W_qkv, wqh, wql, n4);
        n4 = (CC * CC) / 4;
        split_half_kernel<<<n4 / 256, 256>>>(W_proj, wph, wpl, n4);
    }

    // 1) QKV projection (2-term), fused fp16 hi/lo output
    {
        dim3 grid((3 * CC) / 128, MROWS / 128);   // (24, 64)
        gemm_f16_mma<2, true><<<grid, 256, GEMM_SMEM>>>(
            xhi, nullptr, wqh, wql, b_qkv, nullptr, qkvh, qkvl, CC, 3 * CC);
    }

    // 2) Causal flash attention (2-term), fused fp16 hi/lo output
    {
        dim3 grid(TT / 128, BB * NH);             // (16, 64)
        flash_attn_mma<<<grid, 256, ATT_SMEM>>>(qkvh, qkvl, atth, attl);
    }

    // 3) Output projection (3-term) -> fp32 d_out
    {
        dim3 grid(CC / 128, MROWS / 128);         // (8, 64)
        gemm_f16_mma<3, false><<<grid, 256, GEMM_SMEM>>>(
            atth, attl, wph, wpl, b_proj, out, nullptr, nullptr, CC, CC);
    }
}

// round 8
// speedup vs baseline: 5.3554x; 1.2122x over previous
#include <cuda_runtime.h>
#include <cuda_fp16.h>
#include <cstdint>

// Problem constants
#define BB 4
#define TT 2048
#define CC 1024
#define NH 16
#define HD 64
#define MROWS (BB * TT)   // 8192

// ---------------------------------------------------------------------------
// Scratch (device globals — no cudaMalloc allowed)
// ---------------------------------------------------------------------------
__device__ __half g_x_hi[(size_t)MROWS * CC];
__device__ __half g_wqkv_hi[(size_t)3 * CC * CC];
__device__ __half g_wqkv_lo[(size_t)3 * CC * CC];
__device__ __half g_wproj_hi[(size_t)CC * CC];
__device__ __half g_wproj_lo[(size_t)CC * CC];
__device__ __half g_qkv_hi[(size_t)MROWS * 3 * CC];
__device__ __half g_qkv_lo[(size_t)MROWS * 3 * CC];
__device__ __half g_att_hi[(size_t)MROWS * CC];

// ---------------------------------------------------------------------------
// Helpers
// ---------------------------------------------------------------------------
__device__ __forceinline__ uint32_t smem_to_u32(const void* p) {
    uint32_t a;
    asm("{ .reg .u64 t; cvta.to.shared.u64 t, %1; cvt.u32.u64 %0, t; }" : "=r"(a) : "l"(p));
    return a;
}

#define CP_ASYNC_16(dst_u32, src_ptr) \
    asm volatile("cp.async.cg.shared.global [%0], [%1], 16;" \
        :: "r"(dst_u32), "l"(src_ptr) : "memory")
#define CP_ASYNC_COMMIT() asm volatile("cp.async.commit_group;" ::: "memory")
#define CP_ASYNC_WAIT(n)  asm volatile("cp.async.wait_group %0;" :: "n"(n) : "memory")

__device__ __forceinline__ void ldsm4(uint32_t* r, uint32_t addr) {
    asm volatile("ldmatrix.sync.aligned.m8n8.x4.shared.b16 {%0,%1,%2,%3}, [%4];"
        : "=r"(r[0]), "=r"(r[1]), "=r"(r[2]), "=r"(r[3]) : "r"(addr));
}
__device__ __forceinline__ void ldsm4t(uint32_t* r, uint32_t addr) {
    asm volatile("ldmatrix.sync.aligned.m8n8.x4.trans.shared.b16 {%0,%1,%2,%3}, [%4];"
        : "=r"(r[0]), "=r"(r[1]), "=r"(r[2]), "=r"(r[3]) : "r"(addr));
}

__device__ __forceinline__ void mma_f16(float* c, const uint32_t* a, const uint32_t* b) {
    asm volatile(
        "mma.sync.aligned.m16n8k16.row.col.f32.f16.f16.f32 "
        "{%0,%1,%2,%3}, {%4,%5,%6,%7}, {%8,%9}, {%0,%1,%2,%3};"
        : "+f"(c[0]), "+f"(c[1]), "+f"(c[2]), "+f"(c[3])
        : "r"(a[0]), "r"(a[1]), "r"(a[2]), "r"(a[3]), "r"(b[0]), "r"(b[1]));
}

__device__ __forceinline__ uint32_t pack_half(float x, float y) {
    __half2 h = __floats2half2_rn(x, y);
    return *(uint32_t*)&h;
}

// ---------------------------------------------------------------------------
// fp32 -> fp16 convert (hi only)
// ---------------------------------------------------------------------------
__global__ __launch_bounds__(256) void tohalf_kernel(
    const float* __restrict__ in, __half* __restrict__ hi, int n4)
{
    int i = blockIdx.x * blockDim.x + threadIdx.x;
    if (i >= n4) return;
    float4 v = ((const float4*)in)[i];
    ((__half2*)hi)[2 * i]     = __floats2half2_rn(v.x, v.y);
    ((__half2*)hi)[2 * i + 1] = __floats2half2_rn(v.z, v.w);
}

// fp32 -> (fp16 hi, fp16 lo) split
__global__ __launch_bounds__(256) void split_half_kernel(
    const float* __restrict__ in,
    __half* __restrict__ hi, __half* __restrict__ lo, int n4)
{
    int i = blockIdx.x * blockDim.x + threadIdx.x;
    if (i >= n4) return;
    float4 v = ((const float4*)in)[i];
    __half h0 = __float2half_rn(v.x);
    __half h1 = __float2half_rn(v.y);
    __half h2 = __float2half_rn(v.z);
    __half h3 = __float2half_rn(v.w);
    __half2 hA; hA.x = h0; hA.y = h1;
    __half2 hB; hB.x = h2; hB.y = h3;
    ((__half2*)hi)[2 * i]     = hA;
    ((__half2*)hi)[2 * i + 1] = hB;
    __half2 lA = __floats2half2_rn(v.x - __half2float(h0), v.y - __half2float(h1));
    __half2 lB = __floats2half2_rn(v.z - __half2float(h2), v.w - __half2float(h3));
    ((__half2*)lo)[2 * i]     = lA;
    ((__half2*)lo)[2 * i + 1] = lB;
}

// ---------------------------------------------------------------------------
// fp16 Ootomo GEMM via mma.sync:  C[m,n] = sum_k A[m,k]*W[n,k] + bias[n]
// TERMS==2: acc = Ahi*Bhi + Ahi*Blo (3 smem tiles/stage, Alo unused)
// TERMS==3: acc += Alo*Bhi          (4 smem tiles/stage)
// SPLIT: write fp16 hi/lo pair instead of fp32.
// CTA 128x128, BK=32, 8 warps (2m x 4n), cp.async 2-stage,
// __launch_bounds__(256,2) -> <=128 regs -> 2 CTAs/SM (LDSM/MMA overlap).
// ---------------------------------------------------------------------------
#define ROW_B   80
#define TILE_B  (128 * ROW_B)

template<int TERMS, bool SPLIT>
__global__ __launch_bounds__(256, 2) void gemm_f16_mma(
    const __half* __restrict__ Ahi, const __half* __restrict__ Alo,
    const __half* __restrict__ Bhi, const __half* __restrict__ Blo,
    const float* __restrict__ bias,
    float* __restrict__ Cf, __half* __restrict__ Chi, __half* __restrict__ Clo,
    int K, int N)
{
    constexpr int NT = (TERMS == 3) ? 4 : 3;            // tiles per stage
    constexpr uint32_t STAGE = (uint32_t)NT * TILE_B;
    constexpr uint32_t AHI_O = 0;
    constexpr uint32_t ALO_O = TILE_B;                  // only used when TERMS==3
    constexpr uint32_t BHI_O = (uint32_t)(NT - 2) * TILE_B;
    constexpr uint32_t BLO_O = (uint32_t)(NT - 1) * TILE_B;

    extern __shared__ __align__(16) char smem[];
    const uint32_t sbase = smem_to_u32(smem);
    const int tid = threadIdx.x;
    const int wid = tid >> 5;
    const int lid = tid & 31;
    const int wm  = wid & 1;
    const int wn  = wid >> 1;
    const int m0  = blockIdx.y * 128;
    const int n0  = blockIdx.x * 128;

    const int lr = tid >> 2;
    const int cc = tid & 3;
    const uint32_t sm_off = (uint32_t)lr * ROW_B + (uint32_t)cc * 16;
    const int gcol = cc * 8;

    const uint32_t a_off = (uint32_t)(wm * 64 + (lid & 15)) * ROW_B + (uint32_t)(lid >> 4) * 16;
    const uint32_t b_off = (uint32_t)(wn * 32 + ((lid >> 4) << 3) + (lid & 7)) * ROW_B
                         + (uint32_t)((lid >> 3) & 1) * 16;

    float acc[4][4][4];
    #pragma unroll
    for (int i = 0; i < 4; i++)
        #pragma unroll
        for (int n = 0; n < 4; n++)
            #pragma unroll
            for (int v = 0; v < 4; v++)
                acc[i][n][v] = 0.0f;

    const int NCHUNK = K >> 5;

    auto load_stage = [&](int s, int k0) {
        const uint32_t st = sbase + (uint32_t)s * STAGE;
        const size_t ga = (size_t)(m0 + lr) * K + k0 + gcol;
        const size_t gb = (size_t)(n0 + lr) * K + k0 + gcol;
        CP_ASYNC_16(st + AHI_O + sm_off,                 Ahi + ga);
        CP_ASYNC_16(st + AHI_O + sm_off + 64u * ROW_B,   Ahi + ga + (size_t)64 * K);
        if constexpr (TERMS == 3) {
            CP_ASYNC_16(st + ALO_O + sm_off,                 Alo + ga);
            CP_ASYNC_16(st + ALO_O + sm_off + 64u * ROW_B,   Alo + ga + (size_t)64 * K);
        }
        CP_ASYNC_16(st + BHI_O + sm_off,                 Bhi + gb);
        CP_ASYNC_16(st + BHI_O + sm_off + 64u * ROW_B,   Bhi + gb + (size_t)64 * K);
        CP_ASYNC_16(st + BLO_O + sm_off,                 Blo + gb);
        CP_ASYNC_16(st + BLO_O + sm_off + 64u * ROW_B,   Blo + gb + (size_t)64 * K);
    };

    load_stage(0, 0);
    CP_ASYNC_COMMIT();

    for (int c = 0; c < NCHUNK; c++) {
        if (c + 1 < NCHUNK) {
            load_stage((c + 1) & 1, (c + 1) << 5);
            CP_ASYNC_COMMIT();
            CP_ASYNC_WAIT(1);
        } else {
            CP_ASYNC_WAIT(0);
        }
        __syncthreads();

        const uint32_t st  = sbase + (uint32_t)(c & 1) * STAGE;
        const uint32_t aHi = st + AHI_O + a_off;
        const uint32_t aLo = st + ALO_O + a_off;
        const uint32_t bHi = st + BHI_O + b_off;
        const uint32_t bLo = st + BLO_O + b_off;

        #pragma unroll
        for (int kk = 0; kk < 2; kk++) {
            const uint32_t kb = (uint32_t)kk * 32;
            uint32_t ahi[4][4], alo[4][4];
            #pragma unroll
            for (int i = 0; i < 4; i++) {
                ldsm4(ahi[i], aHi + (uint32_t)i * 16 * ROW_B + kb);
                if constexpr (TERMS == 3)
                    ldsm4(alo[i], aLo + (uint32_t)i * 16 * ROW_B + kb);
            }
            uint32_t bhi[2][4], blo[2][4];
            #pragma unroll
            for (int j = 0; j < 2; j++) {
                ldsm4(bhi[j], bHi + (uint32_t)j * 16 * ROW_B + kb);
                ldsm4(blo[j], bLo + (uint32_t)j * 16 * ROW_B + kb);
            }
            #pragma unroll
            for (int i = 0; i < 4; i++) {
                #pragma unroll
                for (int n = 0; n < 4; n++) {
                    const uint32_t* bh = &bhi[n >> 1][(n & 1) * 2];
                    const uint32_t* bl = &blo[n >> 1][(n & 1) * 2];
                    mma_f16(acc[i][n], ahi[i], bh);
                    mma_f16(acc[i][n], ahi[i], bl);
                    if constexpr (TERMS == 3)
                        mma_f16(acc[i][n], alo[i], bh);
                }
            }
        }
        __syncthreads();
    }

    // Epilogue
    const int trow = lid >> 2;
    const int tcol = (lid & 3) * 2;
    #pragma unroll
    for (int i = 0; i < 4; i++) {
        const int r0 = m0 + wm * 64 + i * 16 + trow;
        #pragma unroll
        for (int n = 0; n < 4; n++) {
            const int col = n0 + wn * 32 + n * 8 + tcol;
            const float b0 = bias[col], b1 = bias[col + 1];
            float v00 = acc[i][n][0] + b0, v01 = acc[i][n][1] + b1;
            float v10 = acc[i][n][2] + b0, v11 = acc[i][n][3] + b1;
            if constexpr (SPLIT) {
                __half2 h0 = __floats2half2_rn(v00, v01);
                __half2 h1 = __floats2half2_rn(v10, v11);
                __half2 l0 = __floats2half2_rn(v00 - __half2float(h0.x), v01 - __half2float(h0.y));
                __half2 l1 = __floats2half2_rn(v10 - __half2float(h1.x), v11 - __half2float(h1.y));
                *(__half2*)&Chi[(size_t)r0 * N + col]       = h0;
                *(__half2*)&Chi[(size_t)(r0 + 8) * N + col] = h1;
                *(__half2*)&Clo[(size_t)r0 * N + col]       = l0;
                *(__half2*)&Clo[(size_t)(r0 + 8) * N + col] = l1;
            } else {
                float2 f0; f0.x = v00; f0.y = v01;
                float2 f1; f1.x = v10; f1.y = v11;
                *(float2*)&Cf[(size_t)r0 * N + col]       = f0;
                *(float2*)&Cf[(size_t)(r0 + 8) * N + col] = f1;
            }
        }
    }
}

#define GEMM_SMEM_2T (2 * 3 * TILE_B)   // 61440
#define GEMM_SMEM_3T (2 * 4 * TILE_B)   // 81920

// ---------------------------------------------------------------------------
// Tensor-core flash attention (causal, fp16 2-term Ootomo).
// CTA: 128 q-rows of one (b,h). 8 warps, warp = m16 x n64.
// S = Qhi*Khi + Qhi*Klo ;  O += Phi*Vhi + Phi*Vlo.
// Writes fp16 hi output only (proj GEMM is 2-term, Alo unused).
// ---------------------------------------------------------------------------
#define AROW 144
#define QT_B  (128 * AROW)
#define KVSUB (64 * AROW)
#define KVSTG (4 * KVSUB)
#define ATT_SMEM (QT_B + 2 * KVSTG)   // 92160

__global__ __launch_bounds__(256, 1) void flash_attn_mma(
    const __half* __restrict__ Ghi, const __half* __restrict__ Glo,
    __half* __restrict__ Ohi)
{
    extern __shared__ __align__(16) char smem[];
    const uint32_t sbase = smem_to_u32(smem);
    const int tid = threadIdx.x;
    const int wid = tid >> 5;
    const int lid = tid & 31;
    const int bh  = blockIdx.y;
    const int b   = bh >> 4;
    const int h   = bh & 15;
    const int qblk = (int)gridDim.x - 1 - (int)blockIdx.x;
    const int q0   = qblk * 128;
    const int nkv  = 2 * qblk + 2;

    const uint32_t qhi_s = sbase;
    const uint32_t kv_s  = sbase + QT_B;

    {
        #pragma unroll
        for (int t = 0; t < 4; t++) {
            const int idx = tid + t * 256;
            const int row = idx >> 3;
            const int ch  = idx & 7;
            const __half* src = Ghi + (size_t)(b * TT + q0 + row) * (3 * CC) + h * HD + ch * 8;
            CP_ASYNC_16(qhi_s + (uint32_t)row * AROW + (uint32_t)ch * 16, src);
        }
    }
    auto load_kv = [&](int stage, int kv0) {
        const uint32_t st = kv_s + (uint32_t)stage * KVSTG;
        #pragma unroll
        for (int t = 0; t < 8; t++) {
            const int idx = tid + t * 256;
            const int arr = idx >> 9;            // 0:khi 1:klo 2:vhi 3:vlo
            const int rem = idx & 511;
            const int row = rem >> 3;
            const int ch  = rem & 7;
            const int colbase = ((arr >> 1) ? 2 * CC : CC) + h * HD;
            const __half* src = ((arr & 1) ? Glo : Ghi)
                + (size_t)(b * TT + kv0 + row) * (3 * CC) + colbase + ch * 8;
            CP_ASYNC_16(st + (uint32_t)arr * KVSUB + (uint32_t)row * AROW + (uint32_t)ch * 16, src);
        }
    };

    load_kv(0, 0);
    CP_ASYNC_COMMIT();
    load_kv(1, 64);
    CP_ASYNC_COMMIT();

    const uint32_t a_off = (uint32_t)(wid * 16 + (lid & 15)) * AROW + (uint32_t)(lid >> 4) * 16;
    const uint32_t k_off = (uint32_t)(((lid >> 4) << 3) + (lid & 7)) * AROW + (uint32_t)((lid >> 3) & 1) * 16;
    const uint32_t v_off = (uint32_t)(lid & 15) * AROW + (uint32_t)(lid >> 4) * 16;

    uint32_t qh[4][4];
    float o[8][4];
    #pragma unroll
    for (int n = 0; n < 8; n++)
        #pragma unroll
        for (int v = 0; v < 4; v++) o[n][v] = 0.0f;
    float mi0 = -__int_as_float(0x7f800000), mi1 = mi0;
    float li0 = 0.0f, li1 = 0.0f;

    const int r_lo = wid * 16 + (lid >> 2);
    const int grow0 = q0 + r_lo;
    const int grow1 = grow0 + 8;
    const float NEG_INF = -__int_as_float(0x7f800000);

    for (int t = 0; t < nkv; t++) {
        if (t + 1 < nkv) CP_ASYNC_WAIT(1); else CP_ASYNC_WAIT(0);
        __syncthreads();

        if (t == 0) {
            #pragma unroll
            for (int kk = 0; kk < 4; kk++)
                ldsm4(qh[kk], qhi_s + a_off + (uint32_t)kk * 32);
        }

        const int kv0 = t * 64;
        const uint32_t st   = kv_s + (uint32_t)(t & 1) * KVSTG;
        const uint32_t khiB = st;
        const uint32_t kloB = st + KVSUB;
        const uint32_t vhiB = st + 2 * KVSUB;
        const uint32_t vloB = st + 3 * KVSUB;

        // ---- S = Q K^T (2-term) ----
        float s[8][4];
        #pragma unroll
        for (int n = 0; n < 8; n++)
            #pragma unroll
            for (int v = 0; v < 4; v++) s[n][v] = 0.0f;

        #pragma unroll
        for (int kk = 0; kk < 4; kk++) {
            const uint32_t kb = (uint32_t)kk * 32;
            uint32_t kh[4][4], kl[4][4];
            #pragma unroll
            for (int j = 0; j < 4; j++) {
                ldsm4(kh[j], khiB + k_off + (uint32_t)j * 16 * AROW + kb);
                ldsm4(kl[j], kloB + k_off + (uint32_t)j * 16 * AROW + kb);
            }
            #pragma unroll
            for (int n = 0; n < 8; n++) {
                const uint32_t* bh = &kh[n >> 1][(n & 1) * 2];
                const uint32_t* bl = &kl[n >> 1][(n & 1) * 2];
                mma_f16(s[n], qh[kk], bh);
                mma_f16(s[n], qh[kk], bl);
            }
        }

        // ---- scale + causal mask ----
        const bool need_mask = (kv0 + 63 > q0);
        #pragma unroll
        for (int n = 0; n < 8; n++) {
            #pragma unroll
            for (int v = 0; v < 4; v++) s[n][v] *= 0.125f;
            if (need_mask) {
                const int col = kv0 + n * 8 + (lid & 3) * 2;
                if (col > grow0)     s[n][0] = NEG_INF;
                if (col + 1 > grow0) s[n][1] = NEG_INF;
                if (col > grow1)     s[n][2] = NEG_INF;
                if (col + 1 > grow1) s[n][3] = NEG_INF;
            }
        }

        // ---- online softmax ----
        float mt0 = mi0, mt1 = mi1;
        #pragma unroll
        for (int n = 0; n < 8; n++) {
            mt0 = fmaxf(mt0, fmaxf(s[n][0], s[n][1]));
            mt1 = fmaxf(mt1, fmaxf(s[n][2], s[n][3]));
        }
        mt0 = fmaxf(mt0, __shfl_xor_sync(0xffffffffu, mt0, 1));
        mt0 = fmaxf(mt0, __shfl_xor_sync(0xffffffffu, mt0, 2));
        mt1 = fmaxf(mt1, __shfl_xor_sync(0xffffffffu, mt1, 1));
        mt1 = fmaxf(mt1, __shfl_xor_sync(0xffffffffu, mt1, 2));

        const float rs0 = __expf(mi0 - mt0);
        const float rs1 = __expf(mi1 - mt1);
        mi0 = mt0; mi1 = mt1;
        li0 *= rs0; li1 *= rs1;
        #pragma unroll
        for (int n = 0; n < 8; n++) {
            o[n][0] *= rs0; o[n][1] *= rs0;
            o[n][2] *= rs1; o[n][3] *= rs1;
        }

        uint32_t ph[4][4];
        #pragma unroll
        for (int n = 0; n < 8; n++) {
            float p0 = __expf(s[n][0] - mt0);
            float p1 = __expf(s[n][1] - mt0);
            float p2 = __expf(s[n][2] - mt1);
            float p3 = __expf(s[n][3] - mt1);
            li0 += p0 + p1;
            li1 += p2 + p3;
            const int kk = n >> 1;
            const int hi = (n & 1) * 2;
            ph[kk][hi]     = pack_half(p0, p1);
            ph[kk][hi + 1] = pack_half(p2, p3);
        }

        // ---- O += P V (2-term) ----
        #pragma unroll
        for (int kk = 0; kk < 4; kk++) {
            uint32_t vh[4][4], vl[4][4];
            #pragma unroll
            for (int jp = 0; jp < 4; jp++) {
                const uint32_t off = v_off + (uint32_t)kk * 16 * AROW + (uint32_t)jp * 32;
                ldsm4t(vh[jp], vhiB + off);
                ldsm4t(vl[jp], vloB + off);
            }
            #pragma unroll
            for (int n = 0; n < 8; n++) {
                const uint32_t* bh = &vh[n >> 1][(n & 1) * 2];
                const uint32_t* bl = &vl[n >> 1][(n & 1) * 2];
                mma_f16(o[n], ph[kk], bh);
                mma_f16(o[n], ph[kk], bl);
            }
        }

        __syncthreads();
        if (t + 2 < nkv) {
            load_kv(t & 1, (t + 2) * 64);
            CP_ASYNC_COMMIT();
        }
    }

    // ---- finalize ----
    li0 += __shfl_xor_sync(0xffffffffu, li0, 1);
    li0 += __shfl_xor_sync(0xffffffffu, li0, 2);
    li1 += __shfl_xor_sync(0xffffffffu, li1, 1);
    li1 += __shfl_xor_sync(0xffffffffu, li1, 2);
    const float inv0 = 1.0f / li0;
    const float inv1 = 1.0f / li1;

    #pragma unroll
    for (int n = 0; n < 8; n++) {
        const int gcol = h * HD + n * 8 + (lid & 3) * 2;
        *(__half2*)&Ohi[(size_t)(b * TT + grow0) * CC + gcol] =
            __floats2half2_rn(o[n][0] * inv0, o[n][1] * inv0);
        *(__half2*)&Ohi[(size_t)(b * TT + grow1) * CC + gcol] =
            __floats2half2_rn(o[n][2] * inv1, o[n][3] * inv1);
    }
}

// ---------------------------------------------------------------------------
extern "C" void kernel_launch(void* const* d_in, const int* in_sizes, int n_in,
                              void* d_out, int out_size)
{
    const float* x      = (const float*)d_in[0];
    const float* W_qkv  = (const float*)d_in[1];
    const float* b_qkv  = (const float*)d_in[2];
    const float* W_proj = (const float*)d_in[3];
    const float* b_proj = (const float*)d_in[4];
    float* out = (float*)d_out;

    __half *xhi, *wqh, *wql, *wph, *wpl, *qkvh, *qkvl, *atth;
    cudaGetSymbolAddress((void**)&xhi,  g_x_hi);
    cudaGetSymbolAddress((void**)&wqh,  g_wqkv_hi);
    cudaGetSymbolAddress((void**)&wql,  g_wqkv_lo);
    cudaGetSymbolAddress((void**)&wph,  g_wproj_hi);
    cudaGetSymbolAddress((void**)&wpl,  g_wproj_lo);
    cudaGetSymbolAddress((void**)&qkvh, g_qkv_hi);
    cudaGetSymbolAddress((void**)&qkvl, g_qkv_lo);
    cudaGetSymbolAddress((void**)&atth, g_att_hi);

    static bool attr_set = false;
    if (!attr_set) {
        cudaFuncSetAttribute(gemm_f16_mma<2, true>,
                             cudaFuncAttributeMaxDynamicSharedMemorySize, GEMM_SMEM_2T);
        cudaFuncSetAttribute(gemm_f16_mma<2, false>,
                             cudaFuncAttributeMaxDynamicSharedMemorySize, GEMM_SMEM_2T);
        cudaFuncSetAttribute(flash_attn_mma,
                             cudaFuncAttributeMaxDynamicSharedMemorySize, ATT_SMEM);
        attr_set = true;
    }

    // 0) input conversions
    {
        int n4 = (MROWS * CC) / 4;
        tohalf_kernel<<<n4 / 256, 256>>>(x, xhi, n4);
        n4 = (3 * CC * CC) / 4;
        split_half_kernel<<<n4 / 256, 256>>>(W_qkv, wqh, wql, n4);
        n4 = (CC * CC) / 4;
        split_half_kernel<<<n4 / 256, 256>>>(W_proj, wph, wpl, n4);
    }

    // 1) QKV projection (2-term), fused fp16 hi/lo output
    {
        dim3 grid((3 * CC) / 128, MROWS / 128);   // (24, 64)
        gemm_f16_mma<2, true><<<grid, 256, GEMM_SMEM_2T>>>(
            xhi, nullptr, wqh, wql, b_qkv, nullptr, qkvh, qkvl, CC, 3 * CC);
    }

    // 2) Causal flash attention (2-term), fp16 hi output
    {
        dim3 grid(TT / 128, BB * NH);             // (16, 64)
        flash_attn_mma<<<grid, 256, ATT_SMEM>>>(qkvh, qkvl, atth);
    }

    // 3) Output projection (2-term) -> fp32 d_out
    {
        dim3 grid(CC / 128, MROWS / 128);         // (8, 64)
        gemm_f16_mma<2, false><<<grid, 256, GEMM_SMEM_2T>>>(
            atth, nullptr, wph, wpl, b_proj, out, nullptr, nullptr, CC, CC);
    }
}